// round 9
// baseline (speedup 1.0000x reference)
#include <cuda_runtime.h>
#include <cuda_bf16.h>
#include <math.h>
#include <stdint.h>

#define D_MODEL  1024
#define N_HEADS  16
#define HEAD_DIM 64
#define BATCH    4
#define SEQ      2048
#define M_ROWS   (BATCH * SEQ)   // 8192
#define NELEM    (BATCH * N_HEADS * SEQ * HEAD_DIM)   // 8388608

// ---------------- scratch (static device arrays; no allocation allowed) ----
__device__ float g_Q[NELEM];                 // [B,H,T,Dh] fp32 (pre-rope)
__device__ float g_K[NELEM];
__device__ __nv_bfloat16 g_Xh[NELEM], g_Xl[NELEM];             // split x
__device__ __nv_bfloat16 g_Wh[4 * 1024 * 1024], g_Wl[4 * 1024 * 1024]; // q,k,v,o
__device__ __nv_bfloat16 g_Qh[NELEM], g_Ql[NELEM];             // post-rope split
__device__ __nv_bfloat16 g_Kh[NELEM], g_Kl[NELEM];
__device__ __nv_bfloat16 g_Vh[NELEM], g_Vl[NELEM];             // split V
__device__ __nv_bfloat16 g_Oh[NELEM], g_Ol[NELEM];             // split attn out

// ================= helpers =================================================
__device__ __forceinline__ uint32_t smem_u32(const void* p) {
    uint32_t a;
    asm("{ .reg .u64 t; cvta.to.shared.u64 t, %1; cvt.u32.u64 %0, t; }"
        : "=r"(a) : "l"(p));
    return a;
}
__device__ __forceinline__ void ldsm_x4(uint32_t* r, uint32_t a) {
    asm volatile("ldmatrix.sync.aligned.m8n8.x4.shared.b16 {%0,%1,%2,%3}, [%4];"
                 : "=r"(r[0]), "=r"(r[1]), "=r"(r[2]), "=r"(r[3]) : "r"(a));
}
__device__ __forceinline__ void ldsm_x4_t(uint32_t* r, uint32_t a) {
    asm volatile("ldmatrix.sync.aligned.m8n8.x4.trans.shared.b16 {%0,%1,%2,%3}, [%4];"
                 : "=r"(r[0]), "=r"(r[1]), "=r"(r[2]), "=r"(r[3]) : "r"(a));
}
__device__ __forceinline__ void mma16816(float* c, const uint32_t* a,
                                         uint32_t b0, uint32_t b1) {
    asm volatile("mma.sync.aligned.m16n8k16.row.col.f32.bf16.bf16.f32 "
                 "{%0,%1,%2,%3}, {%4,%5,%6,%7}, {%8,%9}, {%0,%1,%2,%3};"
                 : "+f"(c[0]), "+f"(c[1]), "+f"(c[2]), "+f"(c[3])
                 : "r"(a[0]), "r"(a[1]), "r"(a[2]), "r"(a[3]),
                   "r"(b0), "r"(b1));
}
__device__ __forceinline__ void cp16(uint32_t dst, const void* src) {
    asm volatile("cp.async.cg.shared.global [%0], [%1], 16;"
                 :: "r"(dst), "l"(src));
}
#define CP_COMMIT() asm volatile("cp.async.commit_group;" ::: "memory")
#define CP_WAIT0()  asm volatile("cp.async.wait_group 0;" ::: "memory")
#define CP_WAIT1()  asm volatile("cp.async.wait_group 1;" ::: "memory")

__device__ __forceinline__ void split2(float x, float y,
                                       uint32_t& hi, uint32_t& lo) {
    __nv_bfloat162 h = __floats2bfloat162_rn(x, y);
    hi = *(uint32_t*)&h;
    __nv_bfloat162 l = __floats2bfloat162_rn(x - __bfloat162float(h.x),
                                             y - __bfloat162float(h.y));
    lo = *(uint32_t*)&l;
}
__device__ __forceinline__ void split4_store(__nv_bfloat16* dh, __nv_bfloat16* dl,
                                             float4 v) {
    uint32_t h0, l0, h1, l1;
    split2(v.x, v.y, h0, l0);
    split2(v.z, v.w, h1, l1);
    *(uint2*)dh = make_uint2(h0, h1);
    *(uint2*)dl = make_uint2(l0, l1);
}

// ================= one-shot split kernels ==================================
__global__ void __launch_bounds__(256)
split_x_kernel(const float* __restrict__ x)
{
    int i = blockIdx.x * 256 + threadIdx.x;
    float4 v = ((const float4*)x)[i];
    size_t o = (size_t)i * 4;
    split4_store(g_Xh + o, g_Xl + o, v);
}

__global__ void __launch_bounds__(256)
split_w_kernel(const float* __restrict__ Wq, const float* __restrict__ Wk,
               const float* __restrict__ Wv, const float* __restrict__ Wo)
{
    int i = blockIdx.x * 256 + threadIdx.x;
    int s = i >> 18;
    const float* src = (s == 0) ? Wq : (s == 1) ? Wk : (s == 2) ? Wv : Wo;
    float4 v = ((const float4*)src)[i & 0x3FFFF];
    size_t o = (size_t)i * 4;
    split4_store(g_Wh + o, g_Wl + o, v);
}

// ================= HMMA GEMM, 2-stage cp.async pipeline ====================
// C[128,128] tiles of A[M,1024] @ W[1024,1024]^T ; 3-product hi/lo split.
// K chunk 32; stage = {Ah,Al,Bh,Bl}[128][40] bf16 = 40960 B; 2 stages.
#define GKC   32
#define LDSR2 40
#define TILE_B  10240u                 // bytes per tile [128][40] bf16
#define STAGE_B 40960u                 // 4 tiles
#define GEMM_SMEM (2 * STAGE_B)        // 81920 B
#define NCH   (D_MODEL / GKC)          // 32

__global__ void __launch_bounds__(256, 2)
gemm_bf16_kernel(int a_sel, float* __restrict__ outPlain)
{
    extern __shared__ __nv_bfloat16 ds[];
    const uint32_t sb = smem_u32(ds);

    const int tid  = threadIdx.x;
    const int wid  = tid >> 5;
    const int lane = tid & 31;
    const int wm   = wid >> 2;
    const int wn   = wid & 3;

    const int m0 = blockIdx.y * 128;
    const int n0 = blockIdx.x * 128;

    const __nv_bfloat16* Ah = a_sel ? g_Oh : g_Xh;
    const __nv_bfloat16* Al = a_sel ? g_Ol : g_Xl;
    const int slot = a_sel ? 3 : (int)blockIdx.z;
    const __nv_bfloat16* Wh = g_Wh + ((size_t)slot << 20);
    const __nv_bfloat16* Wl = g_Wl + ((size_t)slot << 20);

    float* dstF = (slot == 0) ? g_Q : g_K;
    const int isV = (slot == 2);

    // per-thread load mapping: 8 cp16 per stage; tile = p>>1
    const int r0_ = tid >> 2,           c0_ = (tid & 3) * 8;
    const int r1_ = (tid + 256) >> 2,   c1_ = ((tid + 256) & 3) * 8;

    const int rA = wm * 64 + (lane & 7) + ((lane >> 3) & 1) * 8;
    const int cA = ((lane >> 4) & 1) * 8;
    const int rowB = (lane & 7) + ((lane >> 4) & 1) * 8;
    const int colB = ((lane >> 3) & 1) * 8;

    float acc[4][4][4];
#pragma unroll
    for (int i = 0; i < 4; i++)
#pragma unroll
        for (int j = 0; j < 4; j++)
#pragma unroll
            for (int q = 0; q < 4; q++) acc[i][j][q] = 0.0f;

    // ---- stage loader ----
    auto load_stage = [&](int ch, int stg) {
        const int k0 = ch * GKC;
        const uint32_t sbase = sb + (uint32_t)stg * STAGE_B;
#pragma unroll
        for (int p = 0; p < 8; p++) {
            const int tile = p >> 1;
            const int r = (p & 1) ? r1_ : r0_;
            const int c = (p & 1) ? c1_ : c0_;
            uint32_t dst = sbase + (uint32_t)tile * TILE_B
                         + (uint32_t)(r * LDSR2 + c) * 2;
            const __nv_bfloat16* src;
            if (tile == 0)      src = Ah + (size_t)(m0 + r) * D_MODEL + k0 + c;
            else if (tile == 1) src = Al + (size_t)(m0 + r) * D_MODEL + k0 + c;
            else if (tile == 2) src = Wh + (size_t)(n0 + r) * D_MODEL + k0 + c;
            else                src = Wl + (size_t)(n0 + r) * D_MODEL + k0 + c;
            cp16(dst, src);
        }
        CP_COMMIT();
    };

    load_stage(0, 0);

    for (int ch = 0; ch < NCH; ch++) {
        const int stg = ch & 1;
        if (ch + 1 < NCH) { load_stage(ch + 1, stg ^ 1); CP_WAIT1(); }
        else              { CP_WAIT0(); }
        __syncthreads();

        const uint32_t aAh = sb + (uint32_t)stg * STAGE_B;
        const uint32_t aAl = aAh + TILE_B;
        const uint32_t aBh = aAh + 2 * TILE_B;
        const uint32_t aBl = aAh + 3 * TILE_B;

#pragma unroll
        for (int ks = 0; ks < 2; ks++) {
            uint32_t ah[4][4], al[4][4];
#pragma unroll
            for (int i = 0; i < 4; i++) {
                uint32_t off = (uint32_t)((rA + i * 16) * LDSR2 + ks * 16 + cA) * 2;
                ldsm_x4(ah[i], aAh + off);
                ldsm_x4(al[i], aAl + off);
            }
#pragma unroll
            for (int jp = 0; jp < 2; jp++) {
                uint32_t bh4[4], bl4[4];
                uint32_t off = (uint32_t)((wn * 32 + jp * 16 + rowB) * LDSR2
                                          + ks * 16 + colB) * 2;
                ldsm_x4(bh4, aBh + off);
                ldsm_x4(bl4, aBl + off);
#pragma unroll
                for (int i = 0; i < 4; i++) {
                    mma16816(acc[i][2 * jp],     ah[i], bh4[0], bh4[1]);
                    mma16816(acc[i][2 * jp],     al[i], bh4[0], bh4[1]);
                    mma16816(acc[i][2 * jp],     ah[i], bl4[0], bl4[1]);
                    mma16816(acc[i][2 * jp + 1], ah[i], bh4[2], bh4[3]);
                    mma16816(acc[i][2 * jp + 1], al[i], bh4[2], bh4[3]);
                    mma16816(acc[i][2 * jp + 1], ah[i], bl4[2], bl4[3]);
                }
            }
        }
        __syncthreads();
    }

#pragma unroll
    for (int i = 0; i < 4; i++) {
#pragma unroll
        for (int j = 0; j < 4; j++) {
            int R0 = m0 + wm * 64 + i * 16 + (lane >> 2);
            int C  = n0 + wn * 32 + j * 8 + (lane & 3) * 2;
            if (a_sel == 0) {
                int hh = C >> 6, d = C & 63;
#pragma unroll
                for (int half = 0; half < 2; half++) {
                    int R = R0 + half * 8;
                    int b = R >> 11, t = R & 2047;
                    size_t o = ((size_t)(b * N_HEADS + hh) * SEQ + t) * HEAD_DIM + d;
                    float v0 = acc[i][j][half * 2], v1 = acc[i][j][half * 2 + 1];
                    if (isV) {
                        uint32_t hi, lo;
                        split2(v0, v1, hi, lo);
                        *(uint32_t*)(g_Vh + o) = hi;
                        *(uint32_t*)(g_Vl + o) = lo;
                    } else {
                        *(float2*)(dstF + o) = make_float2(v0, v1);
                    }
                }
            } else {
#pragma unroll
                for (int half = 0; half < 2; half++) {
                    int R = R0 + half * 8;
                    *(float2*)(outPlain + (size_t)R * D_MODEL + C) =
                        make_float2(acc[i][j][half * 2], acc[i][j][half * 2 + 1]);
                }
            }
        }
    }
}

// ---------------- RoPE + bf16 hi/lo split (scale 1/8 folded into Q) --------
__global__ void __launch_bounds__(256)
rope_split_kernel()
{
    int idx = blockIdx.x * blockDim.x + threadIdx.x;
    int d  = idx & 31;
    int t  = (idx >> 5) & (SEQ - 1);
    int bh = idx >> 16;

    float inv_freq = expf(-(float)d * 0.28782313662425573f);
    float ang = (float)t * inv_freq;
    float s, c;
    sincosf(ang, &s, &c);

    size_t base = ((size_t)bh * SEQ + t) * HEAD_DIM + d;
    float q1 = g_Q[base], q2 = g_Q[base + 32];
    float qa = (q1 * c - q2 * s) * 0.125f;
    float qb = (q2 * c + q1 * s) * 0.125f;
    float k1 = g_K[base], k2 = g_K[base + 32];
    float ka = k1 * c - k2 * s;
    float kb = k2 * c + k1 * s;

    __nv_bfloat16 h;
    h = __float2bfloat16_rn(qa); g_Qh[base] = h;      g_Ql[base]      = __float2bfloat16_rn(qa - __bfloat162float(h));
    h = __float2bfloat16_rn(qb); g_Qh[base + 32] = h; g_Ql[base + 32] = __float2bfloat16_rn(qb - __bfloat162float(h));
    h = __float2bfloat16_rn(ka); g_Kh[base] = h;      g_Kl[base]      = __float2bfloat16_rn(ka - __bfloat162float(h));
    h = __float2bfloat16_rn(kb); g_Kh[base + 32] = h; g_Kl[base + 32] = __float2bfloat16_rn(kb - __bfloat162float(h));
}

// ---------------- Flash attention (causal, HMMA, 2-stage cp.async KV) ------
#define FLD 72
#define QBYTES   36864u                // Qh+Ql [128][72]
#define KVTILE_B 9216u                 // one of Kh/Kl/Vh/Vl [64][72]
#define KVSTG_B  36864u                // 4 tiles
#define FA_SMEM  (QBYTES + 2 * KVSTG_B)   // 110592 B

__global__ void __launch_bounds__(256, 2)
flash_mma_kernel()
{
    extern __shared__ __nv_bfloat16 sb[];
    const uint32_t aQh = smem_u32(sb);
    const uint32_t aQl = aQh + 18432;

    const int tid  = threadIdx.x;
    const int wid  = tid >> 5;
    const int lane = tid & 31;
    const int it   = (int)gridDim.x - 1 - (int)blockIdx.x;   // heavy first
    const int bh   = blockIdx.y;
    const size_t base = (size_t)bh * SEQ * HEAD_DIM;

    // ---- load Q tile (128x64 hi/lo) ----
    {
        const __nv_bfloat16* qh = g_Qh + base + (size_t)it * 128 * 64;
        const __nv_bfloat16* ql = g_Ql + base + (size_t)it * 128 * 64;
#pragma unroll
        for (int p = 0; p < 4; p++) {
            int g = tid + p * 256;
            int r = g >> 3, c8 = (g & 7) * 8;
            cp16(aQh + (uint32_t)(r * FLD + c8) * 2, qh + r * 64 + c8);
            cp16(aQl + (uint32_t)(r * FLD + c8) * 2, ql + r * 64 + c8);
        }
        CP_COMMIT();
    }

    // per-thread KV load mapping (8 cp16 per stage)
    const int kr0 = tid >> 3,          kc0 = (tid & 7) * 8;
    const int kr1 = (tid + 256) >> 3,  kc1 = ((tid + 256) & 7) * 8;

    auto load_kv = [&](int jt, int stg) {
        const size_t kb = base + (size_t)jt * 64 * 64;
        const uint32_t sbase = aQh + QBYTES + (uint32_t)stg * KVSTG_B;
#pragma unroll
        for (int p = 0; p < 8; p++) {
            const int tile = p >> 1;
            const int r = (p & 1) ? kr1 : kr0;
            const int c = (p & 1) ? kc1 : kc0;
            uint32_t dst = sbase + (uint32_t)tile * KVTILE_B
                         + (uint32_t)(r * FLD + c) * 2;
            const __nv_bfloat16* src;
            if (tile == 0)      src = g_Kh + kb + r * 64 + c;
            else if (tile == 1) src = g_Kl + kb + r * 64 + c;
            else if (tile == 2) src = g_Vh + kb + r * 64 + c;
            else                src = g_Vl + kb + r * 64 + c;
            cp16(dst, src);
        }
        CP_COMMIT();
    };

    load_kv(0, 0);

    // ---- Q fragments (WAIT1 -> Q group retired; stage0 may be in flight) ---
    CP_WAIT1();
    __syncthreads();
    uint32_t qh[4][4], ql[4][4];
    {
        int rAq = (lane & 7) + ((lane >> 3) & 1) * 8;
        int cAq = ((lane >> 4) & 1) * 8;
#pragma unroll
        for (int ks = 0; ks < 4; ks++) {
            uint32_t off = (uint32_t)((wid * 16 + rAq) * FLD + ks * 16 + cAq) * 2;
            ldsm_x4(qh[ks], aQh + off);
            ldsm_x4(ql[ks], aQl + off);
        }
    }

    float accO[8][4];
#pragma unroll
    for (int j = 0; j < 8; j++)
#pragma unroll
        for (int q = 0; q < 4; q++) accO[j][q] = 0.0f;
    float m0 = -1e30f, m1 = -1e30f, l0 = 0.0f, l1 = 0.0f;

    const int rowK = (lane & 7) + ((lane >> 4) & 1) * 8;
    const int colK = ((lane >> 3) & 1) * 8;
    const int rowV = (lane & 15);
    const int colV = (lane >> 4) * 8;

    const int jt_end = 2 * it + 1;
    for (int jt = 0; jt <= jt_end; jt++) {
        const int stg = jt & 1;
        if (jt < jt_end) { load_kv(jt + 1, stg ^ 1); CP_WAIT1(); }
        else             { CP_WAIT0(); }
        __syncthreads();

        const uint32_t aKh = aQh + QBYTES + (uint32_t)stg * KVSTG_B;
        const uint32_t aKl = aKh + KVTILE_B;
        const uint32_t aVh = aKh + 2 * KVTILE_B;
        const uint32_t aVl = aKh + 3 * KVTILE_B;

        float s[8][4];
#pragma unroll
        for (int j = 0; j < 8; j++)
#pragma unroll
            for (int q = 0; q < 4; q++) s[j][q] = 0.0f;

#pragma unroll
        for (int ks = 0; ks < 4; ks++) {
#pragma unroll
            for (int pr = 0; pr < 4; pr++) {
                uint32_t kh4[4], kl4[4];
                uint32_t off = (uint32_t)((pr * 16 + rowK) * FLD + ks * 16 + colK) * 2;
                ldsm_x4(kh4, aKh + off);
                ldsm_x4(kl4, aKl + off);
                mma16816(s[2 * pr],     qh[ks], kh4[0], kh4[1]);
                mma16816(s[2 * pr],     ql[ks], kh4[0], kh4[1]);
                mma16816(s[2 * pr],     qh[ks], kl4[0], kl4[1]);
                mma16816(s[2 * pr + 1], qh[ks], kh4[2], kh4[3]);
                mma16816(s[2 * pr + 1], ql[ks], kh4[2], kh4[3]);
                mma16816(s[2 * pr + 1], qh[ks], kl4[2], kl4[3]);
            }
        }

        if (jt >= 2 * it) {
            int row0 = it * 128 + wid * 16 + (lane >> 2);
#pragma unroll
            for (int j = 0; j < 8; j++) {
                int col = jt * 64 + j * 8 + (lane & 3) * 2;
                if (col     > row0)     s[j][0] = -1e30f;
                if (col + 1 > row0)     s[j][1] = -1e30f;
                if (col     > row0 + 8) s[j][2] = -1e30f;
                if (col + 1 > row0 + 8) s[j][3] = -1e30f;
            }
        }

        float mx0 = -1e30f, mx1 = -1e30f;
#pragma unroll
        for (int j = 0; j < 8; j++) {
            mx0 = fmaxf(mx0, fmaxf(s[j][0], s[j][1]));
            mx1 = fmaxf(mx1, fmaxf(s[j][2], s[j][3]));
        }
        mx0 = fmaxf(mx0, __shfl_xor_sync(0xffffffffu, mx0, 1));
        mx0 = fmaxf(mx0, __shfl_xor_sync(0xffffffffu, mx0, 2));
        mx1 = fmaxf(mx1, __shfl_xor_sync(0xffffffffu, mx1, 1));
        mx1 = fmaxf(mx1, __shfl_xor_sync(0xffffffffu, mx1, 2));
        float m0n = fmaxf(m0, mx0), m1n = fmaxf(m1, mx1);
        float r0 = __expf(m0 - m0n);
        float r1 = __expf(m1 - m1n);
        m0 = m0n; m1 = m1n;
        float rs0 = 0.0f, rs1 = 0.0f;
#pragma unroll
        for (int j = 0; j < 8; j++) {
            s[j][0] = __expf(s[j][0] - m0n);
            s[j][1] = __expf(s[j][1] - m0n);
            s[j][2] = __expf(s[j][2] - m1n);
            s[j][3] = __expf(s[j][3] - m1n);
            rs0 += s[j][0] + s[j][1];
            rs1 += s[j][2] + s[j][3];
        }
        rs0 += __shfl_xor_sync(0xffffffffu, rs0, 1);
        rs0 += __shfl_xor_sync(0xffffffffu, rs0, 2);
        rs1 += __shfl_xor_sync(0xffffffffu, rs1, 1);
        rs1 += __shfl_xor_sync(0xffffffffu, rs1, 2);
        l0 = l0 * r0 + rs0;
        l1 = l1 * r1 + rs1;
#pragma unroll
        for (int j = 0; j < 8; j++) {
            accO[j][0] *= r0; accO[j][1] *= r0;
            accO[j][2] *= r1; accO[j][3] *= r1;
        }

#pragma unroll
        for (int ks = 0; ks < 4; ks++) {
            uint32_t ph[4], pl[4];
            split2(s[2 * ks][0],     s[2 * ks][1],     ph[0], pl[0]);
            split2(s[2 * ks][2],     s[2 * ks][3],     ph[1], pl[1]);
            split2(s[2 * ks + 1][0], s[2 * ks + 1][1], ph[2], pl[2]);
            split2(s[2 * ks + 1][2], s[2 * ks + 1][3], ph[3], pl[3]);
#pragma unroll
            for (int dp = 0; dp < 4; dp++) {
                uint32_t vh4[4], vl4[4];
                uint32_t off = (uint32_t)((ks * 16 + rowV) * FLD + dp * 16 + colV) * 2;
                ldsm_x4_t(vh4, aVh + off);
                ldsm_x4_t(vl4, aVl + off);
                mma16816(accO[2 * dp],     ph, vh4[0], vh4[1]);
                mma16816(accO[2 * dp],     pl, vh4[0], vh4[1]);
                mma16816(accO[2 * dp],     ph, vl4[0], vl4[1]);
                mma16816(accO[2 * dp + 1], ph, vh4[2], vh4[3]);
                mma16816(accO[2 * dp + 1], pl, vh4[2], vh4[3]);
                mma16816(accO[2 * dp + 1], ph, vl4[2], vl4[3]);
            }
        }
        __syncthreads();
    }

    // ---- epilogue: O / l -> pre-split bf16 [B,T,D] ----
    float i0 = 1.0f / l0, i1 = 1.0f / l1;
    const int b = bh >> 4, hh = bh & 15;
    const int t0 = it * 128 + wid * 16 + (lane >> 2);
#pragma unroll
    for (int j = 0; j < 8; j++) {
        int d = hh * 64 + j * 8 + (lane & 3) * 2;
        size_t o0 = (size_t)(b * SEQ + t0) * D_MODEL + d;
        size_t o1 = (size_t)(b * SEQ + t0 + 8) * D_MODEL + d;
        uint32_t hi, lo;
        split2(accO[j][0] * i0, accO[j][1] * i0, hi, lo);
        *(uint32_t*)(g_Oh + o0) = hi;
        *(uint32_t*)(g_Ol + o0) = lo;
        split2(accO[j][2] * i1, accO[j][3] * i1, hi, lo);
        *(uint32_t*)(g_Oh + o1) = hi;
        *(uint32_t*)(g_Ol + o1) = lo;
    }
}

// ---------------- launch ----------------------------------------------------
extern "C" void kernel_launch(void* const* d_in, const int* in_sizes, int n_in,
                              void* d_out, int out_size)
{
    const float* x  = (const float*)d_in[0];
    const float* Wq = (const float*)d_in[1];
    const float* Wk = (const float*)d_in[2];
    const float* Wv = (const float*)d_in[3];
    const float* Wo = (const float*)d_in[4];
    float* out = (float*)d_out;

    cudaFuncSetAttribute(gemm_bf16_kernel,
                         cudaFuncAttributeMaxDynamicSharedMemorySize, GEMM_SMEM);
    cudaFuncSetAttribute(flash_mma_kernel,
                         cudaFuncAttributeMaxDynamicSharedMemorySize, FA_SMEM);

    // 0) pre-split inputs to bf16 hi/lo
    split_x_kernel<<<NELEM / 4 / 256, 256>>>(x);
    split_w_kernel<<<(4 * 1024 * 1024) / 4 / 256, 256>>>(Wq, Wk, Wv, Wo);

    // 1) fused QKV projections (grid.z selects weight slot)
    dim3 gq(D_MODEL / 128, M_ROWS / 128, 3);
    gemm_bf16_kernel<<<gq, 256, GEMM_SMEM>>>(0, nullptr);

    // 2) RoPE + hi/lo split on Q (scaled by 1/8) and K
    rope_split_kernel<<<(BATCH * N_HEADS * SEQ * 32) / 256, 256>>>();

    // 3) causal flash attention (HMMA, pipelined) -> g_Oh/g_Ol
    flash_mma_kernel<<<dim3(SEQ / 128, BATCH * N_HEADS), 256, FA_SMEM>>>();

    // 4) output projection: out = O @ Wo^T
    dim3 go(D_MODEL / 128, M_ROWS / 128, 1);
    gemm_bf16_kernel<<<go, 256, GEMM_SMEM>>>(1, out);
}

// round 11
// speedup vs baseline: 1.1925x; 1.1925x over previous
#include <cuda_runtime.h>
#include <cuda_bf16.h>
#include <cuda_fp16.h>
#include <math.h>
#include <stdint.h>

#define D_MODEL  1024
#define N_HEADS  16
#define HEAD_DIM 64
#define BATCH    4
#define SEQ      2048
#define M_ROWS   (BATCH * SEQ)   // 8192
#define NELEM    (BATCH * N_HEADS * SEQ * HEAD_DIM)   // 8388608

// ---------------- scratch (static device arrays; no allocation allowed) ----
__device__ float g_Q[NELEM];                 // [B,H,T,Dh] fp32 (pre-rope)
__device__ float g_K[NELEM];
__device__ __nv_bfloat16 g_Xh[NELEM], g_Xl[NELEM];             // split x
__device__ __nv_bfloat16 g_Wh[4 * 1024 * 1024], g_Wl[4 * 1024 * 1024]; // q,k,v,o
__device__ __nv_bfloat16 g_Qh[NELEM], g_Ql[NELEM];             // post-rope split
__device__ __nv_bfloat16 g_Kh[NELEM], g_Kl[NELEM];
__device__ __half        g_Vf[NELEM];                          // V single fp16
__device__ __nv_bfloat16 g_Oh[NELEM], g_Ol[NELEM];             // split attn out

// ================= helpers =================================================
__device__ __forceinline__ uint32_t smem_u32(const void* p) {
    uint32_t a;
    asm("{ .reg .u64 t; cvta.to.shared.u64 t, %1; cvt.u32.u64 %0, t; }"
        : "=r"(a) : "l"(p));
    return a;
}
__device__ __forceinline__ void ldsm_x4(uint32_t* r, uint32_t a) {
    asm volatile("ldmatrix.sync.aligned.m8n8.x4.shared.b16 {%0,%1,%2,%3}, [%4];"
                 : "=r"(r[0]), "=r"(r[1]), "=r"(r[2]), "=r"(r[3]) : "r"(a));
}
__device__ __forceinline__ void ldsm_x4_t(uint32_t* r, uint32_t a) {
    asm volatile("ldmatrix.sync.aligned.m8n8.x4.trans.shared.b16 {%0,%1,%2,%3}, [%4];"
                 : "=r"(r[0]), "=r"(r[1]), "=r"(r[2]), "=r"(r[3]) : "r"(a));
}
__device__ __forceinline__ void mma16816(float* c, const uint32_t* a,
                                         uint32_t b0, uint32_t b1) {
    asm volatile("mma.sync.aligned.m16n8k16.row.col.f32.bf16.bf16.f32 "
                 "{%0,%1,%2,%3}, {%4,%5,%6,%7}, {%8,%9}, {%0,%1,%2,%3};"
                 : "+f"(c[0]), "+f"(c[1]), "+f"(c[2]), "+f"(c[3])
                 : "r"(a[0]), "r"(a[1]), "r"(a[2]), "r"(a[3]),
                   "r"(b0), "r"(b1));
}
__device__ __forceinline__ void mma16816h(float* c, const uint32_t* a,
                                          uint32_t b0, uint32_t b1) {
    asm volatile("mma.sync.aligned.m16n8k16.row.col.f32.f16.f16.f32 "
                 "{%0,%1,%2,%3}, {%4,%5,%6,%7}, {%8,%9}, {%0,%1,%2,%3};"
                 : "+f"(c[0]), "+f"(c[1]), "+f"(c[2]), "+f"(c[3])
                 : "r"(a[0]), "r"(a[1]), "r"(a[2]), "r"(a[3]),
                   "r"(b0), "r"(b1));
}
__device__ __forceinline__ void split2(float x, float y,
                                       uint32_t& hi, uint32_t& lo) {
    __nv_bfloat162 h = __floats2bfloat162_rn(x, y);
    hi = *(uint32_t*)&h;
    __nv_bfloat162 l = __floats2bfloat162_rn(x - __bfloat162float(h.x),
                                             y - __bfloat162float(h.y));
    lo = *(uint32_t*)&l;
}
__device__ __forceinline__ void split4_store(__nv_bfloat16* dh, __nv_bfloat16* dl,
                                             float4 v) {
    uint32_t h0, l0, h1, l1;
    split2(v.x, v.y, h0, l0);
    split2(v.z, v.w, h1, l1);
    *(uint2*)dh = make_uint2(h0, h1);
    *(uint2*)dl = make_uint2(l0, l1);
}

// ================= one-shot split kernels ==================================
__global__ void __launch_bounds__(256)
split_x_kernel(const float* __restrict__ x)
{
    int i = blockIdx.x * 256 + threadIdx.x;
    float4 v = ((const float4*)x)[i];
    size_t o = (size_t)i * 4;
    split4_store(g_Xh + o, g_Xl + o, v);
}

__global__ void __launch_bounds__(256)
split_w_kernel(const float* __restrict__ Wq, const float* __restrict__ Wk,
               const float* __restrict__ Wv, const float* __restrict__ Wo)
{
    int i = blockIdx.x * 256 + threadIdx.x;
    int s = i >> 18;
    const float* src = (s == 0) ? Wq : (s == 1) ? Wk : (s == 2) ? Wv : Wo;
    float4 v = ((const float4*)src)[i & 0x3FFFF];
    size_t o = (size_t)i * 4;
    split4_store(g_Wh + o, g_Wl + o, v);
}

// ================= HMMA GEMM on pre-split bf16 (R7 baseline) ===============
#define GKC  64
#define LDSR 72
#define GEMM_SMEM (4 * 128 * LDSR * 2)   // 73728 B

__global__ void __launch_bounds__(256, 2)
gemm_bf16_kernel(int a_sel, float* __restrict__ outPlain)
{
    extern __shared__ __nv_bfloat16 ds[];
    __nv_bfloat16* sAh = ds;
    __nv_bfloat16* sAl = ds + 9216;
    __nv_bfloat16* sBh = ds + 18432;
    __nv_bfloat16* sBl = ds + 27648;

    const int tid  = threadIdx.x;
    const int wid  = tid >> 5;
    const int lane = tid & 31;
    const int wm   = wid >> 2;
    const int wn   = wid & 3;

    const int m0 = blockIdx.y * 128;
    const int n0 = blockIdx.x * 128;

    const __nv_bfloat16* Ah = a_sel ? g_Oh : g_Xh;
    const __nv_bfloat16* Al = a_sel ? g_Ol : g_Xl;
    const int slot = a_sel ? 3 : (int)blockIdx.z;
    const __nv_bfloat16* Wh = g_Wh + ((size_t)slot << 20);
    const __nv_bfloat16* Wl = g_Wl + ((size_t)slot << 20);

    float* dstF = (slot == 0) ? g_Q : g_K;
    const int isV = (slot == 2);

    const uint32_t aAh = smem_u32(sAh);
    const uint32_t aAl = aAh + 18432;
    const uint32_t aBh = aAh + 36864;
    const uint32_t aBl = aAh + 55296;

    const int rA   = wm * 64 + (lane & 7) + ((lane >> 3) & 1) * 8;
    const int cA   = ((lane >> 4) & 1) * 8;
    const int rowB = (lane & 7) + ((lane >> 4) & 1) * 8;
    const int colB = ((lane >> 3) & 1) * 8;

    float acc[4][4][4];
#pragma unroll
    for (int i = 0; i < 4; i++)
#pragma unroll
        for (int j = 0; j < 4; j++)
#pragma unroll
            for (int q = 0; q < 4; q++) acc[i][j][q] = 0.0f;

    for (int ch = 0; ch < D_MODEL / GKC; ch++) {
        const int k0 = ch * GKC;
        __syncthreads();
#pragma unroll
        for (int p = 0; p < 4; p++) {
            int g  = tid + p * 256;
            int r  = g >> 3;
            int c8 = (g & 7) * 8;
            int so = r * LDSR + c8;
            *(uint4*)(sAh + so) = *(const uint4*)(Ah + (size_t)(m0 + r) * D_MODEL + k0 + c8);
            *(uint4*)(sAl + so) = *(const uint4*)(Al + (size_t)(m0 + r) * D_MODEL + k0 + c8);
            *(uint4*)(sBh + so) = *(const uint4*)(Wh + (size_t)(n0 + r) * D_MODEL + k0 + c8);
            *(uint4*)(sBl + so) = *(const uint4*)(Wl + (size_t)(n0 + r) * D_MODEL + k0 + c8);
        }
        __syncthreads();

#pragma unroll
        for (int ks = 0; ks < 4; ks++) {
            uint32_t ah[4][4], al[4][4];
#pragma unroll
            for (int i = 0; i < 4; i++) {
                uint32_t off = (uint32_t)((rA + i * 16) * LDSR + ks * 16 + cA) * 2;
                ldsm_x4(ah[i], aAh + off);
                ldsm_x4(al[i], aAl + off);
            }
#pragma unroll
            for (int jp = 0; jp < 2; jp++) {
                uint32_t bh4[4], bl4[4];
                uint32_t off = (uint32_t)((wn * 32 + jp * 16 + rowB) * LDSR
                                          + ks * 16 + colB) * 2;
                ldsm_x4(bh4, aBh + off);
                ldsm_x4(bl4, aBl + off);
#pragma unroll
                for (int i = 0; i < 4; i++) {
                    mma16816(acc[i][2 * jp],     ah[i], bh4[0], bh4[1]);
                    mma16816(acc[i][2 * jp],     al[i], bh4[0], bh4[1]);
                    mma16816(acc[i][2 * jp],     ah[i], bl4[0], bl4[1]);
                    mma16816(acc[i][2 * jp + 1], ah[i], bh4[2], bh4[3]);
                    mma16816(acc[i][2 * jp + 1], al[i], bh4[2], bh4[3]);
                    mma16816(acc[i][2 * jp + 1], ah[i], bl4[2], bl4[3]);
                }
            }
        }
    }

#pragma unroll
    for (int i = 0; i < 4; i++) {
#pragma unroll
        for (int j = 0; j < 4; j++) {
            int R0 = m0 + wm * 64 + i * 16 + (lane >> 2);
            int C  = n0 + wn * 32 + j * 8 + (lane & 3) * 2;
            if (a_sel == 0) {
                int hh = C >> 6, d = C & 63;
#pragma unroll
                for (int half = 0; half < 2; half++) {
                    int R = R0 + half * 8;
                    int b = R >> 11, t = R & 2047;
                    size_t o = ((size_t)(b * N_HEADS + hh) * SEQ + t) * HEAD_DIM + d;
                    float v0 = acc[i][j][half * 2], v1 = acc[i][j][half * 2 + 1];
                    if (isV) {
                        __half2 vh = __floats2half2_rn(v0, v1);
                        *(__half2*)(g_Vf + o) = vh;
                    } else {
                        *(float2*)(dstF + o) = make_float2(v0, v1);
                    }
                }
            } else {
#pragma unroll
                for (int half = 0; half < 2; half++) {
                    int R = R0 + half * 8;
                    *(float2*)(outPlain + (size_t)R * D_MODEL + C) =
                        make_float2(acc[i][j][half * 2], acc[i][j][half * 2 + 1]);
                }
            }
        }
    }
}

// ---------------- RoPE + bf16 hi/lo split (scale 1/8 folded into Q) --------
__global__ void __launch_bounds__(256)
rope_split_kernel()
{
    int idx = blockIdx.x * blockDim.x + threadIdx.x;
    int d  = idx & 31;
    int t  = (idx >> 5) & (SEQ - 1);
    int bh = idx >> 16;

    float inv_freq = expf(-(float)d * 0.28782313662425573f);
    float ang = (float)t * inv_freq;
    float s, c;
    sincosf(ang, &s, &c);

    size_t base = ((size_t)bh * SEQ + t) * HEAD_DIM + d;
    float q1 = g_Q[base], q2 = g_Q[base + 32];
    float qa = (q1 * c - q2 * s) * 0.125f;
    float qb = (q2 * c + q1 * s) * 0.125f;
    float k1 = g_K[base], k2 = g_K[base + 32];
    float ka = k1 * c - k2 * s;
    float kb = k2 * c + k1 * s;

    __nv_bfloat16 h;
    h = __float2bfloat16_rn(qa); g_Qh[base] = h;      g_Ql[base]      = __float2bfloat16_rn(qa - __bfloat162float(h));
    h = __float2bfloat16_rn(qb); g_Qh[base + 32] = h; g_Ql[base + 32] = __float2bfloat16_rn(qb - __bfloat162float(h));
    h = __float2bfloat16_rn(ka); g_Kh[base] = h;      g_Kl[base]      = __float2bfloat16_rn(ka - __bfloat162float(h));
    h = __float2bfloat16_rn(kb); g_Kh[base + 32] = h; g_Kl[base + 32] = __float2bfloat16_rn(kb - __bfloat162float(h));
}

// ---------------- Flash attention (causal) -----------------------------------
// QK^T: bf16 hi/lo 3-product (exact to 2^-16).
// P·V : single fp16 product; P rounded to fp16, row-sum from SAME rounded P.
#define FLD 72
// smem: Qh(18432) Ql(18432) Kh(9216) Kl(9216) Vf(9216) = 64512 B

__global__ void __launch_bounds__(256, 2)
flash_mma_kernel()
{
    extern __shared__ __nv_bfloat16 sb[];
    __nv_bfloat16* sQh = sb;                 // [128][72]
    __nv_bfloat16* sQl = sb + 9216;
    __nv_bfloat16* sKh = sb + 18432;         // [64][72]
    __nv_bfloat16* sKl = sb + 23040;
    __half*        sVf = (__half*)(sb + 27648);   // [64][72] fp16

    const int tid  = threadIdx.x;
    const int wid  = tid >> 5;
    const int lane = tid & 31;
    const int it   = (int)gridDim.x - 1 - (int)blockIdx.x;   // heavy first
    const int bh   = blockIdx.y;
    const size_t base = (size_t)bh * SEQ * HEAD_DIM;

    const uint32_t aQh = smem_u32(sQh);
    const uint32_t aQl = aQh + 18432;
    const uint32_t aKh = aQh + 36864;
    const uint32_t aKl = aQh + 46080;
    const uint32_t aVf = aQh + 55296;

    {
        const __nv_bfloat16* qh = g_Qh + base + (size_t)it * 128 * 64;
        const __nv_bfloat16* ql = g_Ql + base + (size_t)it * 128 * 64;
#pragma unroll
        for (int p = 0; p < 4; p++) {
            int g = tid + p * 256;
            int r = g >> 3, c8 = (g & 7) * 8;
            *(uint4*)(sQh + r * FLD + c8) = *(const uint4*)(qh + r * 64 + c8);
            *(uint4*)(sQl + r * FLD + c8) = *(const uint4*)(ql + r * 64 + c8);
        }
    }
    __syncthreads();

    uint32_t qh[4][4], ql[4][4];
    {
        int rAq = (lane & 7) + ((lane >> 3) & 1) * 8;
        int cAq = ((lane >> 4) & 1) * 8;
#pragma unroll
        for (int ks = 0; ks < 4; ks++) {
            uint32_t off = (uint32_t)((wid * 16 + rAq) * FLD + ks * 16 + cAq) * 2;
            ldsm_x4(qh[ks], aQh + off);
            ldsm_x4(ql[ks], aQl + off);
        }
    }

    float accO[8][4];
#pragma unroll
    for (int j = 0; j < 8; j++)
#pragma unroll
        for (int q = 0; q < 4; q++) accO[j][q] = 0.0f;
    float m0 = -1e30f, m1 = -1e30f, l0 = 0.0f, l1 = 0.0f;

    const int rowK = (lane & 7) + ((lane >> 4) & 1) * 8;
    const int colK = ((lane >> 3) & 1) * 8;
    const int rowV = (lane & 15);
    const int colV = (lane >> 4) * 8;

    const int jt_end = 2 * it + 1;
    for (int jt = 0; jt <= jt_end; jt++) {
        __syncthreads();
        {
            const size_t kb = base + (size_t)jt * 64 * 64;
            // 3 tiles (Kh, Kl, Vf), 2 uint4 per thread per tile
#pragma unroll
            for (int p = 0; p < 2; p++) {
                int g = tid + p * 256;
                int r = g >> 3, c8 = (g & 7) * 8;
                *(uint4*)(sKh + r * FLD + c8) = *(const uint4*)(g_Kh + kb + r * 64 + c8);
                *(uint4*)(sKl + r * FLD + c8) = *(const uint4*)(g_Kl + kb + r * 64 + c8);
                *(uint4*)(sVf + r * FLD + c8) = *(const uint4*)(g_Vf + kb + r * 64 + c8);
            }
        }
        __syncthreads();

        float s[8][4];
#pragma unroll
        for (int j = 0; j < 8; j++)
#pragma unroll
            for (int q = 0; q < 4; q++) s[j][q] = 0.0f;

#pragma unroll
        for (int ks = 0; ks < 4; ks++) {
#pragma unroll
            for (int pr = 0; pr < 4; pr++) {
                uint32_t kh4[4], kl4[4];
                uint32_t off = (uint32_t)((pr * 16 + rowK) * FLD + ks * 16 + colK) * 2;
                ldsm_x4(kh4, aKh + off);
                ldsm_x4(kl4, aKl + off);
                mma16816(s[2 * pr],     qh[ks], kh4[0], kh4[1]);
                mma16816(s[2 * pr],     ql[ks], kh4[0], kh4[1]);
                mma16816(s[2 * pr],     qh[ks], kl4[0], kl4[1]);
                mma16816(s[2 * pr + 1], qh[ks], kh4[2], kh4[3]);
                mma16816(s[2 * pr + 1], ql[ks], kh4[2], kh4[3]);
                mma16816(s[2 * pr + 1], qh[ks], kl4[2], kl4[3]);
            }
        }

        if (jt >= 2 * it) {
            int row0 = it * 128 + wid * 16 + (lane >> 2);
#pragma unroll
            for (int j = 0; j < 8; j++) {
                int col = jt * 64 + j * 8 + (lane & 3) * 2;
                if (col     > row0)     s[j][0] = -1e30f;
                if (col + 1 > row0)     s[j][1] = -1e30f;
                if (col     > row0 + 8) s[j][2] = -1e30f;
                if (col + 1 > row0 + 8) s[j][3] = -1e30f;
            }
        }

        // ---- online softmax; P rounded to fp16, rs summed from rounded P ----
        float mx0 = -1e30f, mx1 = -1e30f;
#pragma unroll
        for (int j = 0; j < 8; j++) {
            mx0 = fmaxf(mx0, fmaxf(s[j][0], s[j][1]));
            mx1 = fmaxf(mx1, fmaxf(s[j][2], s[j][3]));
        }
        mx0 = fmaxf(mx0, __shfl_xor_sync(0xffffffffu, mx0, 1));
        mx0 = fmaxf(mx0, __shfl_xor_sync(0xffffffffu, mx0, 2));
        mx1 = fmaxf(mx1, __shfl_xor_sync(0xffffffffu, mx1, 1));
        mx1 = fmaxf(mx1, __shfl_xor_sync(0xffffffffu, mx1, 2));
        float m0n = fmaxf(m0, mx0), m1n = fmaxf(m1, mx1);
        float r0 = __expf(m0 - m0n);
        float r1 = __expf(m1 - m1n);
        m0 = m0n; m1 = m1n;

        uint32_t parr[8][2];             // packed fp16 P, [j]{rows r,r+8}
        float rs0 = 0.0f, rs1 = 0.0f;
#pragma unroll
        for (int j = 0; j < 8; j++) {
            float e0 = __expf(s[j][0] - m0n);
            float e1 = __expf(s[j][1] - m0n);
            float e2 = __expf(s[j][2] - m1n);
            float e3 = __expf(s[j][3] - m1n);
            __half2 p01 = __floats2half2_rn(e0, e1);
            __half2 p23 = __floats2half2_rn(e2, e3);
            parr[j][0] = *(uint32_t*)&p01;
            parr[j][1] = *(uint32_t*)&p23;
            rs0 += __half2float(p01.x) + __half2float(p01.y);
            rs1 += __half2float(p23.x) + __half2float(p23.y);
        }
        rs0 += __shfl_xor_sync(0xffffffffu, rs0, 1);
        rs0 += __shfl_xor_sync(0xffffffffu, rs0, 2);
        rs1 += __shfl_xor_sync(0xffffffffu, rs1, 1);
        rs1 += __shfl_xor_sync(0xffffffffu, rs1, 2);
        l0 = l0 * r0 + rs0;
        l1 = l1 * r1 + rs1;
#pragma unroll
        for (int j = 0; j < 8; j++) {
            accO[j][0] *= r0; accO[j][1] *= r0;
            accO[j][2] *= r1; accO[j][3] *= r1;
        }

        // ---- O += P(fp16) @ V(fp16)  (single product) ----
#pragma unroll
        for (int ks = 0; ks < 4; ks++) {
            uint32_t ph[4] = { parr[2 * ks][0], parr[2 * ks][1],
                               parr[2 * ks + 1][0], parr[2 * ks + 1][1] };
#pragma unroll
            for (int dp = 0; dp < 4; dp++) {
                uint32_t vf4[4];
                uint32_t off = (uint32_t)((ks * 16 + rowV) * FLD + dp * 16 + colV) * 2;
                ldsm_x4_t(vf4, aVf + off);
                mma16816h(accO[2 * dp],     ph, vf4[0], vf4[1]);
                mma16816h(accO[2 * dp + 1], ph, vf4[2], vf4[3]);
            }
        }
    }

    // ---- epilogue: O / l -> pre-split bf16 [B,T,D] ----
    float i0 = 1.0f / l0, i1 = 1.0f / l1;
    const int b = bh >> 4, hh = bh & 15;
    const int t0 = it * 128 + wid * 16 + (lane >> 2);
#pragma unroll
    for (int j = 0; j < 8; j++) {
        int d = hh * 64 + j * 8 + (lane & 3) * 2;
        size_t o0 = (size_t)(b * SEQ + t0) * D_MODEL + d;
        size_t o1 = (size_t)(b * SEQ + t0 + 8) * D_MODEL + d;
        uint32_t hi, lo;
        split2(accO[j][0] * i0, accO[j][1] * i0, hi, lo);
        *(uint32_t*)(g_Oh + o0) = hi;
        *(uint32_t*)(g_Ol + o0) = lo;
        split2(accO[j][2] * i1, accO[j][3] * i1, hi, lo);
        *(uint32_t*)(g_Oh + o1) = hi;
        *(uint32_t*)(g_Ol + o1) = lo;
    }
}

// ---------------- launch ----------------------------------------------------
extern "C" void kernel_launch(void* const* d_in, const int* in_sizes, int n_in,
                              void* d_out, int out_size)
{
    const float* x  = (const float*)d_in[0];
    const float* Wq = (const float*)d_in[1];
    const float* Wk = (const float*)d_in[2];
    const float* Wv = (const float*)d_in[3];
    const float* Wo = (const float*)d_in[4];
    float* out = (float*)d_out;

    cudaFuncSetAttribute(gemm_bf16_kernel,
                         cudaFuncAttributeMaxDynamicSharedMemorySize, GEMM_SMEM);
    cudaFuncSetAttribute(flash_mma_kernel,
                         cudaFuncAttributeMaxDynamicSharedMemorySize, 64512);

    // 0) pre-split inputs to bf16 hi/lo
    split_x_kernel<<<NELEM / 4 / 256, 256>>>(x);
    split_w_kernel<<<(4 * 1024 * 1024) / 4 / 256, 256>>>(Wq, Wk, Wv, Wo);

    // 1) fused QKV projections (grid.z selects weight slot)
    dim3 gq(D_MODEL / 128, M_ROWS / 128, 3);
    gemm_bf16_kernel<<<gq, 256, GEMM_SMEM>>>(0, nullptr);

    // 2) RoPE + hi/lo split on Q (scaled by 1/8) and K
    rope_split_kernel<<<(BATCH * N_HEADS * SEQ * 32) / 256, 256>>>();

    // 3) causal flash attention (HMMA) -> g_Oh/g_Ol
    flash_mma_kernel<<<dim3(SEQ / 128, BATCH * N_HEADS), 256, 64512>>>();

    // 4) output projection: out = O @ Wo^T
    dim3 go(D_MODEL / 128, M_ROWS / 128, 1);
    gemm_bf16_kernel<<<go, 256, GEMM_SMEM>>>(1, out);
}

// round 12
// speedup vs baseline: 1.2729x; 1.0674x over previous
#include <cuda_runtime.h>
#include <cuda_bf16.h>
#include <cuda_fp16.h>
#include <math.h>
#include <stdint.h>

#define D_MODEL  1024
#define N_HEADS  16
#define HEAD_DIM 64
#define BATCH    4
#define SEQ      2048
#define M_ROWS   (BATCH * SEQ)   // 8192
#define NELEM    (BATCH * N_HEADS * SEQ * HEAD_DIM)   // 8388608

// ---------------- scratch (static device arrays; no allocation allowed) ----
__device__ float g_Q[NELEM];                 // [B,H,T,Dh] fp32 (pre-rope)
__device__ float g_K[NELEM];
__device__ __nv_bfloat16 g_Xh[NELEM], g_Xl[NELEM];             // split x
__device__ __nv_bfloat16 g_Wh[4 * 1024 * 1024], g_Wl[4 * 1024 * 1024]; // q,k,v,o
__device__ __half        g_Q16h[NELEM], g_Q16l[NELEM];         // post-rope fp16 split
__device__ __half        g_K16[NELEM];                         // K single fp16
__device__ __half        g_Vf[NELEM];                          // V single fp16
__device__ __nv_bfloat16 g_Oh[NELEM], g_Ol[NELEM];             // split attn out

// ================= helpers =================================================
__device__ __forceinline__ uint32_t smem_u32(const void* p) {
    uint32_t a;
    asm("{ .reg .u64 t; cvta.to.shared.u64 t, %1; cvt.u32.u64 %0, t; }"
        : "=r"(a) : "l"(p));
    return a;
}
__device__ __forceinline__ void ldsm_x4(uint32_t* r, uint32_t a) {
    asm volatile("ldmatrix.sync.aligned.m8n8.x4.shared.b16 {%0,%1,%2,%3}, [%4];"
                 : "=r"(r[0]), "=r"(r[1]), "=r"(r[2]), "=r"(r[3]) : "r"(a));
}
__device__ __forceinline__ void ldsm_x4_t(uint32_t* r, uint32_t a) {
    asm volatile("ldmatrix.sync.aligned.m8n8.x4.trans.shared.b16 {%0,%1,%2,%3}, [%4];"
                 : "=r"(r[0]), "=r"(r[1]), "=r"(r[2]), "=r"(r[3]) : "r"(a));
}
__device__ __forceinline__ void mma16816(float* c, const uint32_t* a,
                                         uint32_t b0, uint32_t b1) {
    asm volatile("mma.sync.aligned.m16n8k16.row.col.f32.bf16.bf16.f32 "
                 "{%0,%1,%2,%3}, {%4,%5,%6,%7}, {%8,%9}, {%0,%1,%2,%3};"
                 : "+f"(c[0]), "+f"(c[1]), "+f"(c[2]), "+f"(c[3])
                 : "r"(a[0]), "r"(a[1]), "r"(a[2]), "r"(a[3]),
                   "r"(b0), "r"(b1));
}
__device__ __forceinline__ void mma16816h(float* c, const uint32_t* a,
                                          uint32_t b0, uint32_t b1) {
    asm volatile("mma.sync.aligned.m16n8k16.row.col.f32.f16.f16.f32 "
                 "{%0,%1,%2,%3}, {%4,%5,%6,%7}, {%8,%9}, {%0,%1,%2,%3};"
                 : "+f"(c[0]), "+f"(c[1]), "+f"(c[2]), "+f"(c[3])
                 : "r"(a[0]), "r"(a[1]), "r"(a[2]), "r"(a[3]),
                   "r"(b0), "r"(b1));
}
__device__ __forceinline__ void cp16(uint32_t dst, const void* src) {
    asm volatile("cp.async.cg.shared.global [%0], [%1], 16;"
                 :: "r"(dst), "l"(src));
}
#define CP_COMMIT() asm volatile("cp.async.commit_group;" ::: "memory")
#define CP_WAIT0()  asm volatile("cp.async.wait_group 0;" ::: "memory")
#define CP_WAIT1()  asm volatile("cp.async.wait_group 1;" ::: "memory")

__device__ __forceinline__ void split2(float x, float y,
                                       uint32_t& hi, uint32_t& lo) {
    __nv_bfloat162 h = __floats2bfloat162_rn(x, y);
    hi = *(uint32_t*)&h;
    __nv_bfloat162 l = __floats2bfloat162_rn(x - __bfloat162float(h.x),
                                             y - __bfloat162float(h.y));
    lo = *(uint32_t*)&l;
}
__device__ __forceinline__ void split4_store(__nv_bfloat16* dh, __nv_bfloat16* dl,
                                             float4 v) {
    uint32_t h0, l0, h1, l1;
    split2(v.x, v.y, h0, l0);
    split2(v.z, v.w, h1, l1);
    *(uint2*)dh = make_uint2(h0, h1);
    *(uint2*)dl = make_uint2(l0, l1);
}

// ================= one-shot split kernels ==================================
__global__ void __launch_bounds__(256)
split_x_kernel(const float* __restrict__ x)
{
    int i = blockIdx.x * 256 + threadIdx.x;
    float4 v = ((const float4*)x)[i];
    size_t o = (size_t)i * 4;
    split4_store(g_Xh + o, g_Xl + o, v);
}

__global__ void __launch_bounds__(256)
split_w_kernel(const float* __restrict__ Wq, const float* __restrict__ Wk,
               const float* __restrict__ Wv, const float* __restrict__ Wo)
{
    int i = blockIdx.x * 256 + threadIdx.x;
    int s = i >> 18;
    const float* src = (s == 0) ? Wq : (s == 1) ? Wk : (s == 2) ? Wv : Wo;
    float4 v = ((const float4*)src)[i & 0x3FFFF];
    size_t o = (size_t)i * 4;
    split4_store(g_Wh + o, g_Wl + o, v);
}

// ================= HMMA GEMM on pre-split bf16 (R7 baseline) ===============
#define GKC  64
#define LDSR 72
#define GEMM_SMEM (4 * 128 * LDSR * 2)   // 73728 B

__global__ void __launch_bounds__(256, 2)
gemm_bf16_kernel(int a_sel, float* __restrict__ outPlain)
{
    extern __shared__ __nv_bfloat16 ds[];
    __nv_bfloat16* sAh = ds;
    __nv_bfloat16* sAl = ds + 9216;
    __nv_bfloat16* sBh = ds + 18432;
    __nv_bfloat16* sBl = ds + 27648;

    const int tid  = threadIdx.x;
    const int wid  = tid >> 5;
    const int lane = tid & 31;
    const int wm   = wid >> 2;
    const int wn   = wid & 3;

    const int m0 = blockIdx.y * 128;
    const int n0 = blockIdx.x * 128;

    const __nv_bfloat16* Ah = a_sel ? g_Oh : g_Xh;
    const __nv_bfloat16* Al = a_sel ? g_Ol : g_Xl;
    const int slot = a_sel ? 3 : (int)blockIdx.z;
    const __nv_bfloat16* Wh = g_Wh + ((size_t)slot << 20);
    const __nv_bfloat16* Wl = g_Wl + ((size_t)slot << 20);

    float* dstF = (slot == 0) ? g_Q : g_K;
    const int isV = (slot == 2);

    const uint32_t aAh = smem_u32(sAh);
    const uint32_t aAl = aAh + 18432;
    const uint32_t aBh = aAh + 36864;
    const uint32_t aBl = aAh + 55296;

    const int rA   = wm * 64 + (lane & 7) + ((lane >> 3) & 1) * 8;
    const int cA   = ((lane >> 4) & 1) * 8;
    const int rowB = (lane & 7) + ((lane >> 4) & 1) * 8;
    const int colB = ((lane >> 3) & 1) * 8;

    float acc[4][4][4];
#pragma unroll
    for (int i = 0; i < 4; i++)
#pragma unroll
        for (int j = 0; j < 4; j++)
#pragma unroll
            for (int q = 0; q < 4; q++) acc[i][j][q] = 0.0f;

    for (int ch = 0; ch < D_MODEL / GKC; ch++) {
        const int k0 = ch * GKC;
        __syncthreads();
#pragma unroll
        for (int p = 0; p < 4; p++) {
            int g  = tid + p * 256;
            int r  = g >> 3;
            int c8 = (g & 7) * 8;
            int so = r * LDSR + c8;
            *(uint4*)(sAh + so) = *(const uint4*)(Ah + (size_t)(m0 + r) * D_MODEL + k0 + c8);
            *(uint4*)(sAl + so) = *(const uint4*)(Al + (size_t)(m0 + r) * D_MODEL + k0 + c8);
            *(uint4*)(sBh + so) = *(const uint4*)(Wh + (size_t)(n0 + r) * D_MODEL + k0 + c8);
            *(uint4*)(sBl + so) = *(const uint4*)(Wl + (size_t)(n0 + r) * D_MODEL + k0 + c8);
        }
        __syncthreads();

#pragma unroll
        for (int ks = 0; ks < 4; ks++) {
            uint32_t ah[4][4], al[4][4];
#pragma unroll
            for (int i = 0; i < 4; i++) {
                uint32_t off = (uint32_t)((rA + i * 16) * LDSR + ks * 16 + cA) * 2;
                ldsm_x4(ah[i], aAh + off);
                ldsm_x4(al[i], aAl + off);
            }
#pragma unroll
            for (int jp = 0; jp < 2; jp++) {
                uint32_t bh4[4], bl4[4];
                uint32_t off = (uint32_t)((wn * 32 + jp * 16 + rowB) * LDSR
                                          + ks * 16 + colB) * 2;
                ldsm_x4(bh4, aBh + off);
                ldsm_x4(bl4, aBl + off);
#pragma unroll
                for (int i = 0; i < 4; i++) {
                    mma16816(acc[i][2 * jp],     ah[i], bh4[0], bh4[1]);
                    mma16816(acc[i][2 * jp],     al[i], bh4[0], bh4[1]);
                    mma16816(acc[i][2 * jp],     ah[i], bl4[0], bl4[1]);
                    mma16816(acc[i][2 * jp + 1], ah[i], bh4[2], bh4[3]);
                    mma16816(acc[i][2 * jp + 1], al[i], bh4[2], bh4[3]);
                    mma16816(acc[i][2 * jp + 1], ah[i], bl4[2], bl4[3]);
                }
            }
        }
    }

#pragma unroll
    for (int i = 0; i < 4; i++) {
#pragma unroll
        for (int j = 0; j < 4; j++) {
            int R0 = m0 + wm * 64 + i * 16 + (lane >> 2);
            int C  = n0 + wn * 32 + j * 8 + (lane & 3) * 2;
            if (a_sel == 0) {
                int hh = C >> 6, d = C & 63;
#pragma unroll
                for (int half = 0; half < 2; half++) {
                    int R = R0 + half * 8;
                    int b = R >> 11, t = R & 2047;
                    size_t o = ((size_t)(b * N_HEADS + hh) * SEQ + t) * HEAD_DIM + d;
                    float v0 = acc[i][j][half * 2], v1 = acc[i][j][half * 2 + 1];
                    if (isV) {
                        __half2 vh = __floats2half2_rn(v0, v1);
                        *(__half2*)(g_Vf + o) = vh;
                    } else {
                        *(float2*)(dstF + o) = make_float2(v0, v1);
                    }
                }
            } else {
#pragma unroll
                for (int half = 0; half < 2; half++) {
                    int R = R0 + half * 8;
                    *(float2*)(outPlain + (size_t)R * D_MODEL + C) =
                        make_float2(acc[i][j][half * 2], acc[i][j][half * 2 + 1]);
                }
            }
        }
    }
}

// ---------------- RoPE: Q -> fp16 hi/lo (scale 1/8 folded), K -> fp16 ------
__global__ void __launch_bounds__(256)
rope_split_kernel()
{
    int idx = blockIdx.x * blockDim.x + threadIdx.x;
    int d  = idx & 31;
    int t  = (idx >> 5) & (SEQ - 1);
    int bh = idx >> 16;

    float inv_freq = expf(-(float)d * 0.28782313662425573f);
    float ang = (float)t * inv_freq;
    float s, c;
    sincosf(ang, &s, &c);

    size_t base = ((size_t)bh * SEQ + t) * HEAD_DIM + d;
    float q1 = g_Q[base], q2 = g_Q[base + 32];
    float qa = (q1 * c - q2 * s) * 0.125f;
    float qb = (q2 * c + q1 * s) * 0.125f;
    float k1 = g_K[base], k2 = g_K[base + 32];
    float ka = k1 * c - k2 * s;
    float kb = k2 * c + k1 * s;

    __half h;
    h = __float2half_rn(qa); g_Q16h[base]      = h;
    g_Q16l[base]      = __float2half_rn(qa - __half2float(h));
    h = __float2half_rn(qb); g_Q16h[base + 32] = h;
    g_Q16l[base + 32] = __float2half_rn(qb - __half2float(h));
    g_K16[base]      = __float2half_rn(ka);
    g_K16[base + 32] = __float2half_rn(kb);
}

// ---------------- Flash attention (causal) -----------------------------------
// QK^T: fp16 Q hi/lo (2 products) x fp16 K single.
// P·V : single fp16 product; P rounded to fp16, row-sum from SAME rounded P.
// KV double-buffered via cp.async (2-stage).
#define FLD 72
#define QBYTES   36864u                // Q16h+Q16l [128][72]
#define KVTILE_B 9216u                 // one of Kf/Vf [64][72] fp16
#define KVSTG_B  18432u                // 2 tiles
#define FA_SMEM  (QBYTES + 2 * KVSTG_B)   // 73728 B

__global__ void __launch_bounds__(256, 2)
flash_mma_kernel()
{
    extern __shared__ __half sbh[];
    const uint32_t aQh = smem_u32(sbh);
    const uint32_t aQl = aQh + 18432;

    const int tid  = threadIdx.x;
    const int wid  = tid >> 5;
    const int lane = tid & 31;
    const int it   = (int)gridDim.x - 1 - (int)blockIdx.x;   // heavy first
    const int bh   = blockIdx.y;
    const size_t base = (size_t)bh * SEQ * HEAD_DIM;

    // KV cp.async loader: 4 cp16 per thread per stage (Kf, Vf)
    const int kr0 = tid >> 3,          kc0 = (tid & 7) * 8;
    const int kr1 = (tid + 256) >> 3,  kc1 = ((tid + 256) & 7) * 8;
    auto load_kv = [&](int jt, int stg) {
        const size_t kb = base + (size_t)jt * 64 * 64;
        const uint32_t sbase = aQh + QBYTES + (uint32_t)stg * KVSTG_B;
#pragma unroll
        for (int p = 0; p < 4; p++) {
            const int tile = p >> 1;                  // 0 = Kf, 1 = Vf
            const int r = (p & 1) ? kr1 : kr0;
            const int c = (p & 1) ? kc1 : kc0;
            uint32_t dst = sbase + (uint32_t)tile * KVTILE_B
                         + (uint32_t)(r * FLD + c) * 2;
            const __half* src = (tile == 0) ? (g_K16 + kb + r * 64 + c)
                                            : (g_Vf  + kb + r * 64 + c);
            cp16(dst, src);
        }
        CP_COMMIT();
    };

    load_kv(0, 0);   // start KV0 before Q loads

    // ---- load Q tile (128x64 fp16 hi/lo), plain loads ----
    {
        const __half* qh = g_Q16h + base + (size_t)it * 128 * 64;
        const __half* ql = g_Q16l + base + (size_t)it * 128 * 64;
        __half* sQh = sbh;
        __half* sQl = sbh + 9216;
#pragma unroll
        for (int p = 0; p < 4; p++) {
            int g = tid + p * 256;
            int r = g >> 3, c8 = (g & 7) * 8;
            *(uint4*)(sQh + r * FLD + c8) = *(const uint4*)(qh + r * 64 + c8);
            *(uint4*)(sQl + r * FLD + c8) = *(const uint4*)(ql + r * 64 + c8);
        }
    }
    __syncthreads();

    uint32_t qh[4][4], ql[4][4];
    {
        int rAq = (lane & 7) + ((lane >> 3) & 1) * 8;
        int cAq = ((lane >> 4) & 1) * 8;
#pragma unroll
        for (int ks = 0; ks < 4; ks++) {
            uint32_t off = (uint32_t)((wid * 16 + rAq) * FLD + ks * 16 + cAq) * 2;
            ldsm_x4(qh[ks], aQh + off);
            ldsm_x4(ql[ks], aQl + off);
        }
    }

    float accO[8][4];
#pragma unroll
    for (int j = 0; j < 8; j++)
#pragma unroll
        for (int q = 0; q < 4; q++) accO[j][q] = 0.0f;
    float m0 = -1e30f, m1 = -1e30f, l0 = 0.0f, l1 = 0.0f;

    const int rowK = (lane & 7) + ((lane >> 4) & 1) * 8;
    const int colK = ((lane >> 3) & 1) * 8;
    const int rowV = (lane & 15);
    const int colV = (lane >> 4) * 8;

    const int jt_end = 2 * it + 1;
    for (int jt = 0; jt <= jt_end; jt++) {
        const int stg = jt & 1;
        if (jt < jt_end) { load_kv(jt + 1, stg ^ 1); CP_WAIT1(); }
        else             { CP_WAIT0(); }
        __syncthreads();

        const uint32_t aKf = aQh + QBYTES + (uint32_t)stg * KVSTG_B;
        const uint32_t aVf = aKf + KVTILE_B;

        float s[8][4];
#pragma unroll
        for (int j = 0; j < 8; j++)
#pragma unroll
            for (int q = 0; q < 4; q++) s[j][q] = 0.0f;

        // ---- S = (Qh + Ql) @ K^T  (fp16, 2 products) ----
#pragma unroll
        for (int ks = 0; ks < 4; ks++) {
#pragma unroll
            for (int pr = 0; pr < 4; pr++) {
                uint32_t kf4[4];
                uint32_t off = (uint32_t)((pr * 16 + rowK) * FLD + ks * 16 + colK) * 2;
                ldsm_x4(kf4, aKf + off);
                mma16816h(s[2 * pr],     qh[ks], kf4[0], kf4[1]);
                mma16816h(s[2 * pr],     ql[ks], kf4[0], kf4[1]);
                mma16816h(s[2 * pr + 1], qh[ks], kf4[2], kf4[3]);
                mma16816h(s[2 * pr + 1], ql[ks], kf4[2], kf4[3]);
            }
        }

        if (jt >= 2 * it) {
            int row0 = it * 128 + wid * 16 + (lane >> 2);
#pragma unroll
            for (int j = 0; j < 8; j++) {
                int col = jt * 64 + j * 8 + (lane & 3) * 2;
                if (col     > row0)     s[j][0] = -1e30f;
                if (col + 1 > row0)     s[j][1] = -1e30f;
                if (col     > row0 + 8) s[j][2] = -1e30f;
                if (col + 1 > row0 + 8) s[j][3] = -1e30f;
            }
        }

        // ---- online softmax; P rounded to fp16, rs summed from rounded P ----
        float mx0 = -1e30f, mx1 = -1e30f;
#pragma unroll
        for (int j = 0; j < 8; j++) {
            mx0 = fmaxf(mx0, fmaxf(s[j][0], s[j][1]));
            mx1 = fmaxf(mx1, fmaxf(s[j][2], s[j][3]));
        }
        mx0 = fmaxf(mx0, __shfl_xor_sync(0xffffffffu, mx0, 1));
        mx0 = fmaxf(mx0, __shfl_xor_sync(0xffffffffu, mx0, 2));
        mx1 = fmaxf(mx1, __shfl_xor_sync(0xffffffffu, mx1, 1));
        mx1 = fmaxf(mx1, __shfl_xor_sync(0xffffffffu, mx1, 2));
        float m0n = fmaxf(m0, mx0), m1n = fmaxf(m1, mx1);
        float r0 = __expf(m0 - m0n);
        float r1 = __expf(m1 - m1n);
        m0 = m0n; m1 = m1n;

        uint32_t parr[8][2];
        float rs0 = 0.0f, rs1 = 0.0f;
#pragma unroll
        for (int j = 0; j < 8; j++) {
            float e0 = __expf(s[j][0] - m0n);
            float e1 = __expf(s[j][1] - m0n);
            float e2 = __expf(s[j][2] - m1n);
            float e3 = __expf(s[j][3] - m1n);
            __half2 p01 = __floats2half2_rn(e0, e1);
            __half2 p23 = __floats2half2_rn(e2, e3);
            parr[j][0] = *(uint32_t*)&p01;
            parr[j][1] = *(uint32_t*)&p23;
            rs0 += __half2float(p01.x) + __half2float(p01.y);
            rs1 += __half2float(p23.x) + __half2float(p23.y);
        }
        rs0 += __shfl_xor_sync(0xffffffffu, rs0, 1);
        rs0 += __shfl_xor_sync(0xffffffffu, rs0, 2);
        rs1 += __shfl_xor_sync(0xffffffffu, rs1, 1);
        rs1 += __shfl_xor_sync(0xffffffffu, rs1, 2);
        l0 = l0 * r0 + rs0;
        l1 = l1 * r1 + rs1;
#pragma unroll
        for (int j = 0; j < 8; j++) {
            accO[j][0] *= r0; accO[j][1] *= r0;
            accO[j][2] *= r1; accO[j][3] *= r1;
        }

        // ---- O += P(fp16) @ V(fp16) ----
#pragma unroll
        for (int ks = 0; ks < 4; ks++) {
            uint32_t ph[4] = { parr[2 * ks][0], parr[2 * ks][1],
                               parr[2 * ks + 1][0], parr[2 * ks + 1][1] };
#pragma unroll
            for (int dp = 0; dp < 4; dp++) {
                uint32_t vf4[4];
                uint32_t off = (uint32_t)((ks * 16 + rowV) * FLD + dp * 16 + colV) * 2;
                ldsm_x4_t(vf4, aVf + off);
                mma16816h(accO[2 * dp],     ph, vf4[0], vf4[1]);
                mma16816h(accO[2 * dp + 1], ph, vf4[2], vf4[3]);
            }
        }
        __syncthreads();
    }

    // ---- epilogue: O / l -> pre-split bf16 [B,T,D] ----
    float i0 = 1.0f / l0, i1 = 1.0f / l1;
    const int b = bh >> 4, hh = bh & 15;
    const int t0 = it * 128 + wid * 16 + (lane >> 2);
#pragma unroll
    for (int j = 0; j < 8; j++) {
        int d = hh * 64 + j * 8 + (lane & 3) * 2;
        size_t o0 = (size_t)(b * SEQ + t0) * D_MODEL + d;
        size_t o1 = (size_t)(b * SEQ + t0 + 8) * D_MODEL + d;
        uint32_t hi, lo;
        split2(accO[j][0] * i0, accO[j][1] * i0, hi, lo);
        *(uint32_t*)(g_Oh + o0) = hi;
        *(uint32_t*)(g_Ol + o0) = lo;
        split2(accO[j][2] * i1, accO[j][3] * i1, hi, lo);
        *(uint32_t*)(g_Oh + o1) = hi;
        *(uint32_t*)(g_Ol + o1) = lo;
    }
}

// ---------------- launch ----------------------------------------------------
extern "C" void kernel_launch(void* const* d_in, const int* in_sizes, int n_in,
                              void* d_out, int out_size)
{
    const float* x  = (const float*)d_in[0];
    const float* Wq = (const float*)d_in[1];
    const float* Wk = (const float*)d_in[2];
    const float* Wv = (const float*)d_in[3];
    const float* Wo = (const float*)d_in[4];
    float* out = (float*)d_out;

    cudaFuncSetAttribute(gemm_bf16_kernel,
                         cudaFuncAttributeMaxDynamicSharedMemorySize, GEMM_SMEM);
    cudaFuncSetAttribute(flash_mma_kernel,
                         cudaFuncAttributeMaxDynamicSharedMemorySize, FA_SMEM);

    // 0) pre-split inputs to bf16 hi/lo
    split_x_kernel<<<NELEM / 4 / 256, 256>>>(x);
    split_w_kernel<<<(4 * 1024 * 1024) / 4 / 256, 256>>>(Wq, Wk, Wv, Wo);

    // 1) fused QKV projections (grid.z selects weight slot)
    dim3 gq(D_MODEL / 128, M_ROWS / 128, 3);
    gemm_bf16_kernel<<<gq, 256, GEMM_SMEM>>>(0, nullptr);

    // 2) RoPE: Q -> fp16 hi/lo (x 1/8), K -> fp16
    rope_split_kernel<<<(BATCH * N_HEADS * SEQ * 32) / 256, 256>>>();

    // 3) causal flash attention (fp16 HMMA, pipelined KV) -> g_Oh/g_Ol
    flash_mma_kernel<<<dim3(SEQ / 128, BATCH * N_HEADS), 256, FA_SMEM>>>();

    // 4) output projection: out = O @ Wo^T
    dim3 go(D_MODEL / 128, M_ROWS / 128, 1);
    gemm_bf16_kernel<<<go, 256, GEMM_SMEM>>>(1, out);
}

// round 13
// speedup vs baseline: 1.5786x; 1.2402x over previous
#include <cuda_runtime.h>
#include <cuda_bf16.h>
#include <cuda_fp16.h>
#include <math.h>
#include <stdint.h>

#define D_MODEL  1024
#define N_HEADS  16
#define HEAD_DIM 64
#define BATCH    4
#define SEQ      2048
#define M_ROWS   (BATCH * SEQ)   // 8192
#define NELEM    (BATCH * N_HEADS * SEQ * HEAD_DIM)   // 8388608

// ---------------- scratch (static device arrays; no allocation allowed) ----
__device__ float g_Q[NELEM];                 // [B,H,T,Dh] fp32 (pre-rope)
__device__ float g_K[NELEM];
__device__ __half g_Xh[NELEM], g_Xl[NELEM];              // x fp16 hi/lo
__device__ __half g_Wf[4 * 1024 * 1024];                 // W single fp16 (q,k,v,o)
__device__ __half g_Q16h[NELEM], g_Q16l[NELEM];          // post-rope fp16 split
__device__ __half g_K16[NELEM];                          // K single fp16
__device__ __half g_Vf[NELEM];                           // V single fp16
__device__ __half g_Ofh[NELEM], g_Ofl[NELEM];            // attn out fp16 hi/lo

// ================= helpers =================================================
__device__ __forceinline__ uint32_t smem_u32(const void* p) {
    uint32_t a;
    asm("{ .reg .u64 t; cvta.to.shared.u64 t, %1; cvt.u32.u64 %0, t; }"
        : "=r"(a) : "l"(p));
    return a;
}
__device__ __forceinline__ void ldsm_x4(uint32_t* r, uint32_t a) {
    asm volatile("ldmatrix.sync.aligned.m8n8.x4.shared.b16 {%0,%1,%2,%3}, [%4];"
                 : "=r"(r[0]), "=r"(r[1]), "=r"(r[2]), "=r"(r[3]) : "r"(a));
}
__device__ __forceinline__ void ldsm_x4_t(uint32_t* r, uint32_t a) {
    asm volatile("ldmatrix.sync.aligned.m8n8.x4.trans.shared.b16 {%0,%1,%2,%3}, [%4];"
                 : "=r"(r[0]), "=r"(r[1]), "=r"(r[2]), "=r"(r[3]) : "r"(a));
}
__device__ __forceinline__ void mma16816h(float* c, const uint32_t* a,
                                          uint32_t b0, uint32_t b1) {
    asm volatile("mma.sync.aligned.m16n8k16.row.col.f32.f16.f16.f32 "
                 "{%0,%1,%2,%3}, {%4,%5,%6,%7}, {%8,%9}, {%0,%1,%2,%3};"
                 : "+f"(c[0]), "+f"(c[1]), "+f"(c[2]), "+f"(c[3])
                 : "r"(a[0]), "r"(a[1]), "r"(a[2]), "r"(a[3]),
                   "r"(b0), "r"(b1));
}
__device__ __forceinline__ void cp16(uint32_t dst, const void* src) {
    asm volatile("cp.async.cg.shared.global [%0], [%1], 16;"
                 :: "r"(dst), "l"(src));
}
#define CP_COMMIT() asm volatile("cp.async.commit_group;" ::: "memory")
#define CP_WAIT0()  asm volatile("cp.async.wait_group 0;" ::: "memory")
#define CP_WAIT1()  asm volatile("cp.async.wait_group 1;" ::: "memory")

__device__ __forceinline__ void split2h(float x, float y,
                                        uint32_t& hi, uint32_t& lo) {
    __half2 h = __floats2half2_rn(x, y);
    hi = *(uint32_t*)&h;
    __half2 l = __floats2half2_rn(x - __half2float(h.x),
                                  y - __half2float(h.y));
    lo = *(uint32_t*)&l;
}

// ================= one-shot split kernels ==================================
__global__ void __launch_bounds__(256)
split_x_kernel(const float* __restrict__ x)
{
    int i = blockIdx.x * 256 + threadIdx.x;
    float4 v = ((const float4*)x)[i];
    size_t o = (size_t)i * 4;
    uint32_t h0, l0, h1, l1;
    split2h(v.x, v.y, h0, l0);
    split2h(v.z, v.w, h1, l1);
    *(uint2*)(g_Xh + o) = make_uint2(h0, h1);
    *(uint2*)(g_Xl + o) = make_uint2(l0, l1);
}

__global__ void __launch_bounds__(256)
split_w_kernel(const float* __restrict__ Wq, const float* __restrict__ Wk,
               const float* __restrict__ Wv, const float* __restrict__ Wo)
{
    int i = blockIdx.x * 256 + threadIdx.x;
    int s = i >> 18;
    const float* src = (s == 0) ? Wq : (s == 1) ? Wk : (s == 2) ? Wv : Wo;
    float4 v = ((const float4*)src)[i & 0x3FFFF];
    size_t o = (size_t)i * 4;
    __half2 a = __floats2half2_rn(v.x, v.y);
    __half2 b = __floats2half2_rn(v.z, v.w);
    *(uint2*)(g_Wf + o) = make_uint2(*(uint32_t*)&a, *(uint32_t*)&b);
}

// ================= HMMA GEMM, fp16 2-product ===============================
// C[128,128] tiles of A[M,1024] @ W[1024,1024]^T.
// A fp16 hi/lo, W single fp16; smem: 3 tiles [128][72] fp16 = 55296 B.
#define GKC  64
#define LDSR 72
#define GEMM_SMEM (3 * 128 * LDSR * 2)   // 55296 B

__global__ void __launch_bounds__(256, 2)
gemm_fp16_kernel(int a_sel, float* __restrict__ outPlain)
{
    extern __shared__ __half ds[];
    __half* sAh = ds;
    __half* sAl = ds + 9216;
    __half* sBf = ds + 18432;

    const int tid  = threadIdx.x;
    const int wid  = tid >> 5;
    const int lane = tid & 31;
    const int wm   = wid >> 2;
    const int wn   = wid & 3;

    const int m0 = blockIdx.y * 128;
    const int n0 = blockIdx.x * 128;

    const __half* Ah = a_sel ? g_Ofh : g_Xh;
    const __half* Al = a_sel ? g_Ofl : g_Xl;
    const int slot = a_sel ? 3 : (int)blockIdx.z;
    const __half* Wf = g_Wf + ((size_t)slot << 20);

    float* dstF = (slot == 0) ? g_Q : g_K;
    const int isV = (slot == 2);

    const uint32_t aAh = smem_u32(sAh);
    const uint32_t aAl = aAh + 18432;
    const uint32_t aBf = aAh + 36864;

    const int rA   = wm * 64 + (lane & 7) + ((lane >> 3) & 1) * 8;
    const int cA   = ((lane >> 4) & 1) * 8;
    const int rowB = (lane & 7) + ((lane >> 4) & 1) * 8;
    const int colB = ((lane >> 3) & 1) * 8;

    float acc[4][4][4];
#pragma unroll
    for (int i = 0; i < 4; i++)
#pragma unroll
        for (int j = 0; j < 4; j++)
#pragma unroll
            for (int q = 0; q < 4; q++) acc[i][j][q] = 0.0f;

    for (int ch = 0; ch < D_MODEL / GKC; ch++) {
        const int k0 = ch * GKC;
        __syncthreads();
#pragma unroll
        for (int p = 0; p < 4; p++) {
            int g  = tid + p * 256;
            int r  = g >> 3;
            int c8 = (g & 7) * 8;
            int so = r * LDSR + c8;
            *(uint4*)(sAh + so) = *(const uint4*)(Ah + (size_t)(m0 + r) * D_MODEL + k0 + c8);
            *(uint4*)(sAl + so) = *(const uint4*)(Al + (size_t)(m0 + r) * D_MODEL + k0 + c8);
            *(uint4*)(sBf + so) = *(const uint4*)(Wf + (size_t)(n0 + r) * D_MODEL + k0 + c8);
        }
        __syncthreads();

#pragma unroll
        for (int ks = 0; ks < 4; ks++) {
            uint32_t ah[4][4], al[4][4];
#pragma unroll
            for (int i = 0; i < 4; i++) {
                uint32_t off = (uint32_t)((rA + i * 16) * LDSR + ks * 16 + cA) * 2;
                ldsm_x4(ah[i], aAh + off);
                ldsm_x4(al[i], aAl + off);
            }
#pragma unroll
            for (int jp = 0; jp < 2; jp++) {
                uint32_t bf4[4];
                uint32_t off = (uint32_t)((wn * 32 + jp * 16 + rowB) * LDSR
                                          + ks * 16 + colB) * 2;
                ldsm_x4(bf4, aBf + off);
#pragma unroll
                for (int i = 0; i < 4; i++) {
                    mma16816h(acc[i][2 * jp],     ah[i], bf4[0], bf4[1]);
                    mma16816h(acc[i][2 * jp],     al[i], bf4[0], bf4[1]);
                    mma16816h(acc[i][2 * jp + 1], ah[i], bf4[2], bf4[3]);
                    mma16816h(acc[i][2 * jp + 1], al[i], bf4[2], bf4[3]);
                }
            }
        }
    }

#pragma unroll
    for (int i = 0; i < 4; i++) {
#pragma unroll
        for (int j = 0; j < 4; j++) {
            int R0 = m0 + wm * 64 + i * 16 + (lane >> 2);
            int C  = n0 + wn * 32 + j * 8 + (lane & 3) * 2;
            if (a_sel == 0) {
                int hh = C >> 6, d = C & 63;
#pragma unroll
                for (int half = 0; half < 2; half++) {
                    int R = R0 + half * 8;
                    int b = R >> 11, t = R & 2047;
                    size_t o = ((size_t)(b * N_HEADS + hh) * SEQ + t) * HEAD_DIM + d;
                    float v0 = acc[i][j][half * 2], v1 = acc[i][j][half * 2 + 1];
                    if (isV) {
                        __half2 vh = __floats2half2_rn(v0, v1);
                        *(__half2*)(g_Vf + o) = vh;
                    } else {
                        *(float2*)(dstF + o) = make_float2(v0, v1);
                    }
                }
            } else {
#pragma unroll
                for (int half = 0; half < 2; half++) {
                    int R = R0 + half * 8;
                    *(float2*)(outPlain + (size_t)R * D_MODEL + C) =
                        make_float2(acc[i][j][half * 2], acc[i][j][half * 2 + 1]);
                }
            }
        }
    }
}

// ---------------- RoPE: Q -> fp16 hi/lo (scale 0.125*log2e), K -> fp16 ------
__global__ void __launch_bounds__(256)
rope_split_kernel()
{
    int idx = blockIdx.x * blockDim.x + threadIdx.x;
    int d  = idx & 31;
    int t  = (idx >> 5) & (SEQ - 1);
    int bh = idx >> 16;

    float inv_freq = expf(-(float)d * 0.28782313662425573f);
    float ang = (float)t * inv_freq;
    float s, c;
    sincosf(ang, &s, &c);

    const float QS = 0.18033688011112042f;   // 0.125 * log2(e)
    size_t base = ((size_t)bh * SEQ + t) * HEAD_DIM + d;
    float q1 = g_Q[base], q2 = g_Q[base + 32];
    float qa = (q1 * c - q2 * s) * QS;
    float qb = (q2 * c + q1 * s) * QS;
    float k1 = g_K[base], k2 = g_K[base + 32];
    float ka = k1 * c - k2 * s;
    float kb = k2 * c + k1 * s;

    __half h;
    h = __float2half_rn(qa); g_Q16h[base]      = h;
    g_Q16l[base]      = __float2half_rn(qa - __half2float(h));
    h = __float2half_rn(qb); g_Q16h[base + 32] = h;
    g_Q16l[base + 32] = __float2half_rn(qb - __half2float(h));
    g_K16[base]      = __float2half_rn(ka);
    g_K16[base + 32] = __float2half_rn(kb);
}

// ---------------- Flash attention (causal, base-2 softmax) -------------------
// QK^T: fp16 Q hi/lo (2 products) x fp16 K single; S already in log2 units.
// P·V : single fp16 product; P = exp2(s - m), row-sum from rounded P.
#define FLD 72
#define QBYTES   36864u                // Q16h+Q16l [128][72]
#define KVTILE_B 9216u                 // one of Kf/Vf [64][72] fp16
#define KVSTG_B  18432u                // 2 tiles
#define FA_SMEM  (QBYTES + 2 * KVSTG_B)   // 73728 B

__global__ void __launch_bounds__(256, 2)
flash_mma_kernel()
{
    extern __shared__ __half sbh[];
    const uint32_t aQh = smem_u32(sbh);
    const uint32_t aQl = aQh + 18432;

    const int tid  = threadIdx.x;
    const int wid  = tid >> 5;
    const int lane = tid & 31;
    const int it   = (int)gridDim.x - 1 - (int)blockIdx.x;   // heavy first
    const int bh   = blockIdx.y;
    const size_t base = (size_t)bh * SEQ * HEAD_DIM;

    const int kr0 = tid >> 3,          kc0 = (tid & 7) * 8;
    const int kr1 = (tid + 256) >> 3,  kc1 = ((tid + 256) & 7) * 8;
    auto load_kv = [&](int jt, int stg) {
        const size_t kb = base + (size_t)jt * 64 * 64;
        const uint32_t sbase = aQh + QBYTES + (uint32_t)stg * KVSTG_B;
#pragma unroll
        for (int p = 0; p < 4; p++) {
            const int tile = p >> 1;                  // 0 = Kf, 1 = Vf
            const int r = (p & 1) ? kr1 : kr0;
            const int c = (p & 1) ? kc1 : kc0;
            uint32_t dst = sbase + (uint32_t)tile * KVTILE_B
                         + (uint32_t)(r * FLD + c) * 2;
            const __half* src = (tile == 0) ? (g_K16 + kb + r * 64 + c)
                                            : (g_Vf  + kb + r * 64 + c);
            cp16(dst, src);
        }
        CP_COMMIT();
    };

    load_kv(0, 0);

    {
        const __half* qh = g_Q16h + base + (size_t)it * 128 * 64;
        const __half* ql = g_Q16l + base + (size_t)it * 128 * 64;
        __half* sQh = sbh;
        __half* sQl = sbh + 9216;
#pragma unroll
        for (int p = 0; p < 4; p++) {
            int g = tid + p * 256;
            int r = g >> 3, c8 = (g & 7) * 8;
            *(uint4*)(sQh + r * FLD + c8) = *(const uint4*)(qh + r * 64 + c8);
            *(uint4*)(sQl + r * FLD + c8) = *(const uint4*)(ql + r * 64 + c8);
        }
    }
    __syncthreads();

    uint32_t qh[4][4], ql[4][4];
    {
        int rAq = (lane & 7) + ((lane >> 3) & 1) * 8;
        int cAq = ((lane >> 4) & 1) * 8;
#pragma unroll
        for (int ks = 0; ks < 4; ks++) {
            uint32_t off = (uint32_t)((wid * 16 + rAq) * FLD + ks * 16 + cAq) * 2;
            ldsm_x4(qh[ks], aQh + off);
            ldsm_x4(ql[ks], aQl + off);
        }
    }

    float accO[8][4];
#pragma unroll
    for (int j = 0; j < 8; j++)
#pragma unroll
        for (int q = 0; q < 4; q++) accO[j][q] = 0.0f;
    float m0 = -1e30f, m1 = -1e30f, l0 = 0.0f, l1 = 0.0f;

    const int rowK = (lane & 7) + ((lane >> 4) & 1) * 8;
    const int colK = ((lane >> 3) & 1) * 8;
    const int rowV = (lane & 15);
    const int colV = (lane >> 4) * 8;

    const int jt_end = 2 * it + 1;
    for (int jt = 0; jt <= jt_end; jt++) {
        const int stg = jt & 1;
        if (jt < jt_end) { load_kv(jt + 1, stg ^ 1); CP_WAIT1(); }
        else             { CP_WAIT0(); }
        __syncthreads();

        const uint32_t aKf = aQh + QBYTES + (uint32_t)stg * KVSTG_B;
        const uint32_t aVf = aKf + KVTILE_B;

        float s[8][4];
#pragma unroll
        for (int j = 0; j < 8; j++)
#pragma unroll
            for (int q = 0; q < 4; q++) s[j][q] = 0.0f;

#pragma unroll
        for (int ks = 0; ks < 4; ks++) {
#pragma unroll
            for (int pr = 0; pr < 4; pr++) {
                uint32_t kf4[4];
                uint32_t off = (uint32_t)((pr * 16 + rowK) * FLD + ks * 16 + colK) * 2;
                ldsm_x4(kf4, aKf + off);
                mma16816h(s[2 * pr],     qh[ks], kf4[0], kf4[1]);
                mma16816h(s[2 * pr],     ql[ks], kf4[0], kf4[1]);
                mma16816h(s[2 * pr + 1], qh[ks], kf4[2], kf4[3]);
                mma16816h(s[2 * pr + 1], ql[ks], kf4[2], kf4[3]);
            }
        }

        if (jt >= 2 * it) {
            int row0 = it * 128 + wid * 16 + (lane >> 2);
#pragma unroll
            for (int j = 0; j < 8; j++) {
                int col = jt * 64 + j * 8 + (lane & 3) * 2;
                if (col     > row0)     s[j][0] = -1e30f;
                if (col + 1 > row0)     s[j][1] = -1e30f;
                if (col     > row0 + 8) s[j][2] = -1e30f;
                if (col + 1 > row0 + 8) s[j][3] = -1e30f;
            }
        }

        // ---- online softmax (base-2); P fp16, rs summed from rounded P ----
        float mx0 = -1e30f, mx1 = -1e30f;
#pragma unroll
        for (int j = 0; j < 8; j++) {
            mx0 = fmaxf(mx0, fmaxf(s[j][0], s[j][1]));
            mx1 = fmaxf(mx1, fmaxf(s[j][2], s[j][3]));
        }
        mx0 = fmaxf(mx0, __shfl_xor_sync(0xffffffffu, mx0, 1));
        mx0 = fmaxf(mx0, __shfl_xor_sync(0xffffffffu, mx0, 2));
        mx1 = fmaxf(mx1, __shfl_xor_sync(0xffffffffu, mx1, 1));
        mx1 = fmaxf(mx1, __shfl_xor_sync(0xffffffffu, mx1, 2));
        float m0n = fmaxf(m0, mx0), m1n = fmaxf(m1, mx1);
        float r0 = exp2f(m0 - m0n);
        float r1 = exp2f(m1 - m1n);
        m0 = m0n; m1 = m1n;

        uint32_t parr[8][2];
        float rs0 = 0.0f, rs1 = 0.0f;
#pragma unroll
        for (int j = 0; j < 8; j++) {
            float e0 = exp2f(s[j][0] - m0n);
            float e1 = exp2f(s[j][1] - m0n);
            float e2 = exp2f(s[j][2] - m1n);
            float e3 = exp2f(s[j][3] - m1n);
            __half2 p01 = __floats2half2_rn(e0, e1);
            __half2 p23 = __floats2half2_rn(e2, e3);
            parr[j][0] = *(uint32_t*)&p01;
            parr[j][1] = *(uint32_t*)&p23;
            rs0 += __half2float(p01.x) + __half2float(p01.y);
            rs1 += __half2float(p23.x) + __half2float(p23.y);
        }
        rs0 += __shfl_xor_sync(0xffffffffu, rs0, 1);
        rs0 += __shfl_xor_sync(0xffffffffu, rs0, 2);
        rs1 += __shfl_xor_sync(0xffffffffu, rs1, 1);
        rs1 += __shfl_xor_sync(0xffffffffu, rs1, 2);
        l0 = l0 * r0 + rs0;
        l1 = l1 * r1 + rs1;
#pragma unroll
        for (int j = 0; j < 8; j++) {
            accO[j][0] *= r0; accO[j][1] *= r0;
            accO[j][2] *= r1; accO[j][3] *= r1;
        }

        // ---- O += P(fp16) @ V(fp16) ----
#pragma unroll
        for (int ks = 0; ks < 4; ks++) {
            uint32_t ph[4] = { parr[2 * ks][0], parr[2 * ks][1],
                               parr[2 * ks + 1][0], parr[2 * ks + 1][1] };
#pragma unroll
            for (int dp = 0; dp < 4; dp++) {
                uint32_t vf4[4];
                uint32_t off = (uint32_t)((ks * 16 + rowV) * FLD + dp * 16 + colV) * 2;
                ldsm_x4_t(vf4, aVf + off);
                mma16816h(accO[2 * dp],     ph, vf4[0], vf4[1]);
                mma16816h(accO[2 * dp + 1], ph, vf4[2], vf4[3]);
            }
        }
        __syncthreads();
    }

    // ---- epilogue: O / l -> fp16 hi/lo [B,T,D] ----
    float i0 = 1.0f / l0, i1 = 1.0f / l1;
    const int b = bh >> 4, hh = bh & 15;
    const int t0 = it * 128 + wid * 16 + (lane >> 2);
#pragma unroll
    for (int j = 0; j < 8; j++) {
        int d = hh * 64 + j * 8 + (lane & 3) * 2;
        size_t o0 = (size_t)(b * SEQ + t0) * D_MODEL + d;
        size_t o1 = (size_t)(b * SEQ + t0 + 8) * D_MODEL + d;
        uint32_t hi, lo;
        split2h(accO[j][0] * i0, accO[j][1] * i0, hi, lo);
        *(uint32_t*)(g_Ofh + o0) = hi;
        *(uint32_t*)(g_Ofl + o0) = lo;
        split2h(accO[j][2] * i1, accO[j][3] * i1, hi, lo);
        *(uint32_t*)(g_Ofh + o1) = hi;
        *(uint32_t*)(g_Ofl + o1) = lo;
    }
}

// ---------------- launch ----------------------------------------------------
extern "C" void kernel_launch(void* const* d_in, const int* in_sizes, int n_in,
                              void* d_out, int out_size)
{
    const float* x  = (const float*)d_in[0];
    const float* Wq = (const float*)d_in[1];
    const float* Wk = (const float*)d_in[2];
    const float* Wv = (const float*)d_in[3];
    const float* Wo = (const float*)d_in[4];
    float* out = (float*)d_out;

    cudaFuncSetAttribute(gemm_fp16_kernel,
                         cudaFuncAttributeMaxDynamicSharedMemorySize, GEMM_SMEM);
    cudaFuncSetAttribute(flash_mma_kernel,
                         cudaFuncAttributeMaxDynamicSharedMemorySize, FA_SMEM);

    // 0) pre-split inputs to fp16
    split_x_kernel<<<NELEM / 4 / 256, 256>>>(x);
    split_w_kernel<<<(4 * 1024 * 1024) / 4 / 256, 256>>>(Wq, Wk, Wv, Wo);

    // 1) fused QKV projections (grid.z selects weight slot)
    dim3 gq(D_MODEL / 128, M_ROWS / 128, 3);
    gemm_fp16_kernel<<<gq, 256, GEMM_SMEM>>>(0, nullptr);

    // 2) RoPE: Q -> fp16 hi/lo (x 0.125*log2e), K -> fp16
    rope_split_kernel<<<(BATCH * N_HEADS * SEQ * 32) / 256, 256>>>();

    // 3) causal flash attention (fp16 HMMA, base-2 softmax) -> g_Ofh/g_Ofl
    flash_mma_kernel<<<dim3(SEQ / 128, BATCH * N_HEADS), 256, FA_SMEM>>>();

    // 4) output projection: out = O @ Wo^T
    dim3 go(D_MODEL / 128, M_ROWS / 128, 1);
    gemm_fp16_kernel<<<go, 256, GEMM_SMEM>>>(1, out);
}

// round 14
// speedup vs baseline: 1.6880x; 1.0693x over previous
#include <cuda_runtime.h>
#include <cuda_bf16.h>
#include <cuda_fp16.h>
#include <math.h>
#include <stdint.h>

#define D_MODEL  1024
#define N_HEADS  16
#define HEAD_DIM 64
#define BATCH    4
#define SEQ      2048
#define M_ROWS   (BATCH * SEQ)   // 8192
#define NELEM    (BATCH * N_HEADS * SEQ * HEAD_DIM)   // 8388608

// ---------------- scratch (static device arrays; no allocation allowed) ----
__device__ float g_Q[NELEM];                 // [B,H,T,Dh] fp32 (pre-rope)
__device__ float g_K[NELEM];
__device__ __half g_Xh[NELEM], g_Xl[NELEM];              // x fp16 hi/lo
__device__ __half g_Wf[4 * 1024 * 1024];                 // W single fp16 (q,k,v,o)
__device__ __half g_Q16[NELEM];                          // post-rope Q fp16
__device__ __half g_K16[NELEM];                          // K single fp16
__device__ __half g_Vf[NELEM];                           // V single fp16
__device__ __half g_Ofh[NELEM], g_Ofl[NELEM];            // attn out fp16 hi/lo

// ================= helpers =================================================
__device__ __forceinline__ uint32_t smem_u32(const void* p) {
    uint32_t a;
    asm("{ .reg .u64 t; cvta.to.shared.u64 t, %1; cvt.u32.u64 %0, t; }"
        : "=r"(a) : "l"(p));
    return a;
}
__device__ __forceinline__ void ldsm_x4(uint32_t* r, uint32_t a) {
    asm volatile("ldmatrix.sync.aligned.m8n8.x4.shared.b16 {%0,%1,%2,%3}, [%4];"
                 : "=r"(r[0]), "=r"(r[1]), "=r"(r[2]), "=r"(r[3]) : "r"(a));
}
__device__ __forceinline__ void ldsm_x4_t(uint32_t* r, uint32_t a) {
    asm volatile("ldmatrix.sync.aligned.m8n8.x4.trans.shared.b16 {%0,%1,%2,%3}, [%4];"
                 : "=r"(r[0]), "=r"(r[1]), "=r"(r[2]), "=r"(r[3]) : "r"(a));
}
__device__ __forceinline__ void mma16816h(float* c, const uint32_t* a,
                                          uint32_t b0, uint32_t b1) {
    asm volatile("mma.sync.aligned.m16n8k16.row.col.f32.f16.f16.f32 "
                 "{%0,%1,%2,%3}, {%4,%5,%6,%7}, {%8,%9}, {%0,%1,%2,%3};"
                 : "+f"(c[0]), "+f"(c[1]), "+f"(c[2]), "+f"(c[3])
                 : "r"(a[0]), "r"(a[1]), "r"(a[2]), "r"(a[3]),
                   "r"(b0), "r"(b1));
}
__device__ __forceinline__ void cp16(uint32_t dst, const void* src) {
    asm volatile("cp.async.cg.shared.global [%0], [%1], 16;"
                 :: "r"(dst), "l"(src));
}
#define CP_COMMIT() asm volatile("cp.async.commit_group;" ::: "memory")
#define CP_WAIT0()  asm volatile("cp.async.wait_group 0;" ::: "memory")
#define CP_WAIT1()  asm volatile("cp.async.wait_group 1;" ::: "memory")

__device__ __forceinline__ void split2h(float x, float y,
                                        uint32_t& hi, uint32_t& lo) {
    __half2 h = __floats2half2_rn(x, y);
    hi = *(uint32_t*)&h;
    __half2 l = __floats2half2_rn(x - __half2float(h.x),
                                  y - __half2float(h.y));
    lo = *(uint32_t*)&l;
}

// ================= one-shot split kernels ==================================
__global__ void __launch_bounds__(256)
split_x_kernel(const float* __restrict__ x)
{
    int i = blockIdx.x * 256 + threadIdx.x;
    float4 v = ((const float4*)x)[i];
    size_t o = (size_t)i * 4;
    uint32_t h0, l0, h1, l1;
    split2h(v.x, v.y, h0, l0);
    split2h(v.z, v.w, h1, l1);
    *(uint2*)(g_Xh + o) = make_uint2(h0, h1);
    *(uint2*)(g_Xl + o) = make_uint2(l0, l1);
}

__global__ void __launch_bounds__(256)
split_w_kernel(const float* __restrict__ Wq, const float* __restrict__ Wk,
               const float* __restrict__ Wv, const float* __restrict__ Wo)
{
    int i = blockIdx.x * 256 + threadIdx.x;
    int s = i >> 18;
    const float* src = (s == 0) ? Wq : (s == 1) ? Wk : (s == 2) ? Wv : Wo;
    float4 v = ((const float4*)src)[i & 0x3FFFF];
    size_t o = (size_t)i * 4;
    __half2 a = __floats2half2_rn(v.x, v.y);
    __half2 b = __floats2half2_rn(v.z, v.w);
    *(uint2*)(g_Wf + o) = make_uint2(*(uint32_t*)&a, *(uint32_t*)&b);
}

// ================= HMMA GEMM, fp16 2-product ===============================
#define GKC  64
#define LDSR 72
#define GEMM_SMEM (3 * 128 * LDSR * 2)   // 55296 B

__global__ void __launch_bounds__(256, 2)
gemm_fp16_kernel(int a_sel, float* __restrict__ outPlain)
{
    extern __shared__ __half ds[];
    __half* sAh = ds;
    __half* sAl = ds + 9216;
    __half* sBf = ds + 18432;

    const int tid  = threadIdx.x;
    const int wid  = tid >> 5;
    const int lane = tid & 31;
    const int wm   = wid >> 2;
    const int wn   = wid & 3;

    const int m0 = blockIdx.y * 128;
    const int n0 = blockIdx.x * 128;

    const __half* Ah = a_sel ? g_Ofh : g_Xh;
    const __half* Al = a_sel ? g_Ofl : g_Xl;
    const int slot = a_sel ? 3 : (int)blockIdx.z;
    const __half* Wf = g_Wf + ((size_t)slot << 20);

    float* dstF = (slot == 0) ? g_Q : g_K;
    const int isV = (slot == 2);

    const uint32_t aAh = smem_u32(sAh);
    const uint32_t aAl = aAh + 18432;
    const uint32_t aBf = aAh + 36864;

    const int rA   = wm * 64 + (lane & 7) + ((lane >> 3) & 1) * 8;
    const int cA   = ((lane >> 4) & 1) * 8;
    const int rowB = (lane & 7) + ((lane >> 4) & 1) * 8;
    const int colB = ((lane >> 3) & 1) * 8;

    float acc[4][4][4];
#pragma unroll
    for (int i = 0; i < 4; i++)
#pragma unroll
        for (int j = 0; j < 4; j++)
#pragma unroll
            for (int q = 0; q < 4; q++) acc[i][j][q] = 0.0f;

    for (int ch = 0; ch < D_MODEL / GKC; ch++) {
        const int k0 = ch * GKC;
        __syncthreads();
#pragma unroll
        for (int p = 0; p < 4; p++) {
            int g  = tid + p * 256;
            int r  = g >> 3;
            int c8 = (g & 7) * 8;
            int so = r * LDSR + c8;
            *(uint4*)(sAh + so) = *(const uint4*)(Ah + (size_t)(m0 + r) * D_MODEL + k0 + c8);
            *(uint4*)(sAl + so) = *(const uint4*)(Al + (size_t)(m0 + r) * D_MODEL + k0 + c8);
            *(uint4*)(sBf + so) = *(const uint4*)(Wf + (size_t)(n0 + r) * D_MODEL + k0 + c8);
        }
        __syncthreads();

#pragma unroll
        for (int ks = 0; ks < 4; ks++) {
            uint32_t ah[4][4], al[4][4];
#pragma unroll
            for (int i = 0; i < 4; i++) {
                uint32_t off = (uint32_t)((rA + i * 16) * LDSR + ks * 16 + cA) * 2;
                ldsm_x4(ah[i], aAh + off);
                ldsm_x4(al[i], aAl + off);
            }
#pragma unroll
            for (int jp = 0; jp < 2; jp++) {
                uint32_t bf4[4];
                uint32_t off = (uint32_t)((wn * 32 + jp * 16 + rowB) * LDSR
                                          + ks * 16 + colB) * 2;
                ldsm_x4(bf4, aBf + off);
#pragma unroll
                for (int i = 0; i < 4; i++) {
                    mma16816h(acc[i][2 * jp],     ah[i], bf4[0], bf4[1]);
                    mma16816h(acc[i][2 * jp],     al[i], bf4[0], bf4[1]);
                    mma16816h(acc[i][2 * jp + 1], ah[i], bf4[2], bf4[3]);
                    mma16816h(acc[i][2 * jp + 1], al[i], bf4[2], bf4[3]);
                }
            }
        }
    }

#pragma unroll
    for (int i = 0; i < 4; i++) {
#pragma unroll
        for (int j = 0; j < 4; j++) {
            int R0 = m0 + wm * 64 + i * 16 + (lane >> 2);
            int C  = n0 + wn * 32 + j * 8 + (lane & 3) * 2;
            if (a_sel == 0) {
                int hh = C >> 6, d = C & 63;
#pragma unroll
                for (int half = 0; half < 2; half++) {
                    int R = R0 + half * 8;
                    int b = R >> 11, t = R & 2047;
                    size_t o = ((size_t)(b * N_HEADS + hh) * SEQ + t) * HEAD_DIM + d;
                    float v0 = acc[i][j][half * 2], v1 = acc[i][j][half * 2 + 1];
                    if (isV) {
                        __half2 vh = __floats2half2_rn(v0, v1);
                        *(__half2*)(g_Vf + o) = vh;
                    } else {
                        *(float2*)(dstF + o) = make_float2(v0, v1);
                    }
                }
            } else {
#pragma unroll
                for (int half = 0; half < 2; half++) {
                    int R = R0 + half * 8;
                    *(float2*)(outPlain + (size_t)R * D_MODEL + C) =
                        make_float2(acc[i][j][half * 2], acc[i][j][half * 2 + 1]);
                }
            }
        }
    }
}

// ---------------- RoPE: Q -> fp16 (scale 0.125*log2e), K -> fp16 -----------
__global__ void __launch_bounds__(256)
rope_split_kernel()
{
    int idx = blockIdx.x * blockDim.x + threadIdx.x;
    int d  = idx & 31;
    int t  = (idx >> 5) & (SEQ - 1);
    int bh = idx >> 16;

    float inv_freq = expf(-(float)d * 0.28782313662425573f);
    float ang = (float)t * inv_freq;
    float s, c;
    sincosf(ang, &s, &c);

    const float QS = 0.18033688011112042f;   // 0.125 * log2(e)
    size_t base = ((size_t)bh * SEQ + t) * HEAD_DIM + d;
    float q1 = g_Q[base], q2 = g_Q[base + 32];
    float qa = (q1 * c - q2 * s) * QS;
    float qb = (q2 * c + q1 * s) * QS;
    float k1 = g_K[base], k2 = g_K[base + 32];
    float ka = k1 * c - k2 * s;
    float kb = k2 * c + k1 * s;

    g_Q16[base]      = __float2half_rn(qa);
    g_Q16[base + 32] = __float2half_rn(qb);
    g_K16[base]      = __float2half_rn(ka);
    g_K16[base + 32] = __float2half_rn(kb);
}

// ---------------- Flash attention (causal, base-2 softmax) -------------------
// QK^T: single fp16 product. P·V: single fp16 product (P fp16, rs from
// rounded P). KV double-buffered via cp.async.
#define FLD 72
#define QBYTES   18432u                // Q fp16 [128][72]
#define KVTILE_B 9216u                 // one of Kf/Vf [64][72] fp16
#define KVSTG_B  18432u                // 2 tiles
#define FA_SMEM  (QBYTES + 2 * KVSTG_B)   // 55296 B

__global__ void __launch_bounds__(256, 2)
flash_mma_kernel()
{
    extern __shared__ __half sbh[];
    const uint32_t aQf = smem_u32(sbh);

    const int tid  = threadIdx.x;
    const int wid  = tid >> 5;
    const int lane = tid & 31;
    const int it   = (int)gridDim.x - 1 - (int)blockIdx.x;   // heavy first
    const int bh   = blockIdx.y;
    const size_t base = (size_t)bh * SEQ * HEAD_DIM;

    const int kr0 = tid >> 3,          kc0 = (tid & 7) * 8;
    const int kr1 = (tid + 256) >> 3,  kc1 = ((tid + 256) & 7) * 8;
    auto load_kv = [&](int jt, int stg) {
        const size_t kb = base + (size_t)jt * 64 * 64;
        const uint32_t sbase = aQf + QBYTES + (uint32_t)stg * KVSTG_B;
#pragma unroll
        for (int p = 0; p < 4; p++) {
            const int tile = p >> 1;                  // 0 = Kf, 1 = Vf
            const int r = (p & 1) ? kr1 : kr0;
            const int c = (p & 1) ? kc1 : kc0;
            uint32_t dst = sbase + (uint32_t)tile * KVTILE_B
                         + (uint32_t)(r * FLD + c) * 2;
            const __half* src = (tile == 0) ? (g_K16 + kb + r * 64 + c)
                                            : (g_Vf  + kb + r * 64 + c);
            cp16(dst, src);
        }
        CP_COMMIT();
    };

    load_kv(0, 0);

    {
        const __half* qf = g_Q16 + base + (size_t)it * 128 * 64;
#pragma unroll
        for (int p = 0; p < 4; p++) {
            int g = tid + p * 256;
            int r = g >> 3, c8 = (g & 7) * 8;
            *(uint4*)(sbh + r * FLD + c8) = *(const uint4*)(qf + r * 64 + c8);
        }
    }
    __syncthreads();

    uint32_t qf[4][4];
    {
        int rAq = (lane & 7) + ((lane >> 3) & 1) * 8;
        int cAq = ((lane >> 4) & 1) * 8;
#pragma unroll
        for (int ks = 0; ks < 4; ks++) {
            uint32_t off = (uint32_t)((wid * 16 + rAq) * FLD + ks * 16 + cAq) * 2;
            ldsm_x4(qf[ks], aQf + off);
        }
    }

    float accO[8][4];
#pragma unroll
    for (int j = 0; j < 8; j++)
#pragma unroll
        for (int q = 0; q < 4; q++) accO[j][q] = 0.0f;
    float m0 = -1e30f, m1 = -1e30f, l0 = 0.0f, l1 = 0.0f;

    const int rowK = (lane & 7) + ((lane >> 4) & 1) * 8;
    const int colK = ((lane >> 3) & 1) * 8;
    const int rowV = (lane & 15);
    const int colV = (lane >> 4) * 8;

    const int jt_end = 2 * it + 1;
    for (int jt = 0; jt <= jt_end; jt++) {
        const int stg = jt & 1;
        if (jt < jt_end) { load_kv(jt + 1, stg ^ 1); CP_WAIT1(); }
        else             { CP_WAIT0(); }
        __syncthreads();

        const uint32_t aKf = aQf + QBYTES + (uint32_t)stg * KVSTG_B;
        const uint32_t aVf = aKf + KVTILE_B;

        float s[8][4];
#pragma unroll
        for (int j = 0; j < 8; j++)
#pragma unroll
            for (int q = 0; q < 4; q++) s[j][q] = 0.0f;

        // ---- S = Q @ K^T  (single fp16 product) ----
#pragma unroll
        for (int ks = 0; ks < 4; ks++) {
#pragma unroll
            for (int pr = 0; pr < 4; pr++) {
                uint32_t kf4[4];
                uint32_t off = (uint32_t)((pr * 16 + rowK) * FLD + ks * 16 + colK) * 2;
                ldsm_x4(kf4, aKf + off);
                mma16816h(s[2 * pr],     qf[ks], kf4[0], kf4[1]);
                mma16816h(s[2 * pr + 1], qf[ks], kf4[2], kf4[3]);
            }
        }

        if (jt >= 2 * it) {
            int row0 = it * 128 + wid * 16 + (lane >> 2);
#pragma unroll
            for (int j = 0; j < 8; j++) {
                int col = jt * 64 + j * 8 + (lane & 3) * 2;
                if (col     > row0)     s[j][0] = -1e30f;
                if (col + 1 > row0)     s[j][1] = -1e30f;
                if (col     > row0 + 8) s[j][2] = -1e30f;
                if (col + 1 > row0 + 8) s[j][3] = -1e30f;
            }
        }

        // ---- online softmax (base-2); P fp16, rs summed from rounded P ----
        float mx0 = -1e30f, mx1 = -1e30f;
#pragma unroll
        for (int j = 0; j < 8; j++) {
            mx0 = fmaxf(mx0, fmaxf(s[j][0], s[j][1]));
            mx1 = fmaxf(mx1, fmaxf(s[j][2], s[j][3]));
        }
        mx0 = fmaxf(mx0, __shfl_xor_sync(0xffffffffu, mx0, 1));
        mx0 = fmaxf(mx0, __shfl_xor_sync(0xffffffffu, mx0, 2));
        mx1 = fmaxf(mx1, __shfl_xor_sync(0xffffffffu, mx1, 1));
        mx1 = fmaxf(mx1, __shfl_xor_sync(0xffffffffu, mx1, 2));
        float m0n = fmaxf(m0, mx0), m1n = fmaxf(m1, mx1);
        float r0 = exp2f(m0 - m0n);
        float r1 = exp2f(m1 - m1n);
        m0 = m0n; m1 = m1n;

        uint32_t parr[8][2];
        float rs0 = 0.0f, rs1 = 0.0f;
#pragma unroll
        for (int j = 0; j < 8; j++) {
            float e0 = exp2f(s[j][0] - m0n);
            float e1 = exp2f(s[j][1] - m0n);
            float e2 = exp2f(s[j][2] - m1n);
            float e3 = exp2f(s[j][3] - m1n);
            __half2 p01 = __floats2half2_rn(e0, e1);
            __half2 p23 = __floats2half2_rn(e2, e3);
            parr[j][0] = *(uint32_t*)&p01;
            parr[j][1] = *(uint32_t*)&p23;
            rs0 += __half2float(p01.x) + __half2float(p01.y);
            rs1 += __half2float(p23.x) + __half2float(p23.y);
        }
        rs0 += __shfl_xor_sync(0xffffffffu, rs0, 1);
        rs0 += __shfl_xor_sync(0xffffffffu, rs0, 2);
        rs1 += __shfl_xor_sync(0xffffffffu, rs1, 1);
        rs1 += __shfl_xor_sync(0xffffffffu, rs1, 2);
        l0 = l0 * r0 + rs0;
        l1 = l1 * r1 + rs1;
#pragma unroll
        for (int j = 0; j < 8; j++) {
            accO[j][0] *= r0; accO[j][1] *= r0;
            accO[j][2] *= r1; accO[j][3] *= r1;
        }

        // ---- O += P(fp16) @ V(fp16) ----
#pragma unroll
        for (int ks = 0; ks < 4; ks++) {
            uint32_t ph[4] = { parr[2 * ks][0], parr[2 * ks][1],
                               parr[2 * ks + 1][0], parr[2 * ks + 1][1] };
#pragma unroll
            for (int dp = 0; dp < 4; dp++) {
                uint32_t vf4[4];
                uint32_t off = (uint32_t)((ks * 16 + rowV) * FLD + dp * 16 + colV) * 2;
                ldsm_x4_t(vf4, aVf + off);
                mma16816h(accO[2 * dp],     ph, vf4[0], vf4[1]);
                mma16816h(accO[2 * dp + 1], ph, vf4[2], vf4[3]);
            }
        }
        __syncthreads();
    }

    // ---- epilogue: O / l -> fp16 hi/lo [B,T,D] ----
    float i0 = 1.0f / l0, i1 = 1.0f / l1;
    const int b = bh >> 4, hh = bh & 15;
    const int t0 = it * 128 + wid * 16 + (lane >> 2);
#pragma unroll
    for (int j = 0; j < 8; j++) {
        int d = hh * 64 + j * 8 + (lane & 3) * 2;
        size_t o0 = (size_t)(b * SEQ + t0) * D_MODEL + d;
        size_t o1 = (size_t)(b * SEQ + t0 + 8) * D_MODEL + d;
        uint32_t hi, lo;
        split2h(accO[j][0] * i0, accO[j][1] * i0, hi, lo);
        *(uint32_t*)(g_Ofh + o0) = hi;
        *(uint32_t*)(g_Ofl + o0) = lo;
        split2h(accO[j][2] * i1, accO[j][3] * i1, hi, lo);
        *(uint32_t*)(g_Ofh + o1) = hi;
        *(uint32_t*)(g_Ofl + o1) = lo;
    }
}

// ---------------- launch ----------------------------------------------------
extern "C" void kernel_launch(void* const* d_in, const int* in_sizes, int n_in,
                              void* d_out, int out_size)
{
    const float* x  = (const float*)d_in[0];
    const float* Wq = (const float*)d_in[1];
    const float* Wk = (const float*)d_in[2];
    const float* Wv = (const float*)d_in[3];
    const float* Wo = (const float*)d_in[4];
    float* out = (float*)d_out;

    cudaFuncSetAttribute(gemm_fp16_kernel,
                         cudaFuncAttributeMaxDynamicSharedMemorySize, GEMM_SMEM);
    cudaFuncSetAttribute(flash_mma_kernel,
                         cudaFuncAttributeMaxDynamicSharedMemorySize, FA_SMEM);

    // 0) pre-split inputs to fp16
    split_x_kernel<<<NELEM / 4 / 256, 256>>>(x);
    split_w_kernel<<<(4 * 1024 * 1024) / 4 / 256, 256>>>(Wq, Wk, Wv, Wo);

    // 1) fused QKV projections (grid.z selects weight slot)
    dim3 gq(D_MODEL / 128, M_ROWS / 128, 3);
    gemm_fp16_kernel<<<gq, 256, GEMM_SMEM>>>(0, nullptr);

    // 2) RoPE: Q -> fp16 (x 0.125*log2e), K -> fp16
    rope_split_kernel<<<(BATCH * N_HEADS * SEQ * 32) / 256, 256>>>();

    // 3) causal flash attention (fp16 HMMA, base-2 softmax) -> g_Ofh/g_Ofl
    flash_mma_kernel<<<dim3(SEQ / 128, BATCH * N_HEADS), 256, FA_SMEM>>>();

    // 4) output projection: out = O @ Wo^T
    dim3 go(D_MODEL / 128, M_ROWS / 128, 1);
    gemm_fp16_kernel<<<go, 256, GEMM_SMEM>>>(1, out);
}

// round 15
// speedup vs baseline: 1.7141x; 1.0155x over previous
#include <cuda_runtime.h>
#include <cuda_bf16.h>
#include <cuda_fp16.h>
#include <math.h>
#include <stdint.h>

#define D_MODEL  1024
#define N_HEADS  16
#define HEAD_DIM 64
#define BATCH    4
#define SEQ      2048
#define M_ROWS   (BATCH * SEQ)   // 8192
#define NELEM    (BATCH * N_HEADS * SEQ * HEAD_DIM)   // 8388608

// ---------------- scratch (static device arrays; no allocation allowed) ----
__device__ float g_Q[NELEM];                 // [B,H,T,Dh] fp32 (pre-rope)
__device__ float g_K[NELEM];
__device__ __half g_Xh[NELEM], g_Xl[NELEM];              // x fp16 hi/lo
__device__ __half g_Wf[4 * 1024 * 1024];                 // W single fp16 (q,k,v,o)
__device__ __half g_Q16[NELEM];                          // post-rope Q fp16
__device__ __half g_K16[NELEM];                          // K single fp16
__device__ __half g_Vf[NELEM];                           // V single fp16
__device__ __half g_Ofh[NELEM], g_Ofl[NELEM];            // attn out fp16 hi/lo

// ================= helpers =================================================
__device__ __forceinline__ uint32_t smem_u32(const void* p) {
    uint32_t a;
    asm("{ .reg .u64 t; cvta.to.shared.u64 t, %1; cvt.u32.u64 %0, t; }"
        : "=r"(a) : "l"(p));
    return a;
}
__device__ __forceinline__ void ldsm_x4(uint32_t* r, uint32_t a) {
    asm volatile("ldmatrix.sync.aligned.m8n8.x4.shared.b16 {%0,%1,%2,%3}, [%4];"
                 : "=r"(r[0]), "=r"(r[1]), "=r"(r[2]), "=r"(r[3]) : "r"(a));
}
__device__ __forceinline__ void ldsm_x4_t(uint32_t* r, uint32_t a) {
    asm volatile("ldmatrix.sync.aligned.m8n8.x4.trans.shared.b16 {%0,%1,%2,%3}, [%4];"
                 : "=r"(r[0]), "=r"(r[1]), "=r"(r[2]), "=r"(r[3]) : "r"(a));
}
__device__ __forceinline__ void ldsm_x2_t(uint32_t* r, uint32_t a) {
    asm volatile("ldmatrix.sync.aligned.m8n8.x2.trans.shared.b16 {%0,%1}, [%2];"
                 : "=r"(r[0]), "=r"(r[1]) : "r"(a));
}
__device__ __forceinline__ void mma16816h(float* c, const uint32_t* a,
                                          uint32_t b0, uint32_t b1) {
    asm volatile("mma.sync.aligned.m16n8k16.row.col.f32.f16.f16.f32 "
                 "{%0,%1,%2,%3}, {%4,%5,%6,%7}, {%8,%9}, {%0,%1,%2,%3};"
                 : "+f"(c[0]), "+f"(c[1]), "+f"(c[2]), "+f"(c[3])
                 : "r"(a[0]), "r"(a[1]), "r"(a[2]), "r"(a[3]),
                   "r"(b0), "r"(b1));
}
__device__ __forceinline__ void cp16(uint32_t dst, const void* src) {
    asm volatile("cp.async.cg.shared.global [%0], [%1], 16;"
                 :: "r"(dst), "l"(src));
}
#define CP_COMMIT() asm volatile("cp.async.commit_group;" ::: "memory")
#define CP_WAIT0()  asm volatile("cp.async.wait_group 0;" ::: "memory")
#define CP_WAIT1()  asm volatile("cp.async.wait_group 1;" ::: "memory")

__device__ __forceinline__ void split2h(float x, float y,
                                        uint32_t& hi, uint32_t& lo) {
    __half2 h = __floats2half2_rn(x, y);
    hi = *(uint32_t*)&h;
    __half2 l = __floats2half2_rn(x - __half2float(h.x),
                                  y - __half2float(h.y));
    lo = *(uint32_t*)&l;
}

// ================= one-shot split kernels ==================================
__global__ void __launch_bounds__(256)
split_x_kernel(const float* __restrict__ x)
{
    int i = blockIdx.x * 256 + threadIdx.x;
    float4 v = ((const float4*)x)[i];
    size_t o = (size_t)i * 4;
    uint32_t h0, l0, h1, l1;
    split2h(v.x, v.y, h0, l0);
    split2h(v.z, v.w, h1, l1);
    *(uint2*)(g_Xh + o) = make_uint2(h0, h1);
    *(uint2*)(g_Xl + o) = make_uint2(l0, l1);
}

__global__ void __launch_bounds__(256)
split_w_kernel(const float* __restrict__ Wq, const float* __restrict__ Wk,
               const float* __restrict__ Wv, const float* __restrict__ Wo)
{
    int i = blockIdx.x * 256 + threadIdx.x;
    int s = i >> 18;
    const float* src = (s == 0) ? Wq : (s == 1) ? Wk : (s == 2) ? Wv : Wo;
    float4 v = ((const float4*)src)[i & 0x3FFFF];
    size_t o = (size_t)i * 4;
    __half2 a = __floats2half2_rn(v.x, v.y);
    __half2 b = __floats2half2_rn(v.z, v.w);
    *(uint2*)(g_Wf + o) = make_uint2(*(uint32_t*)&a, *(uint32_t*)&b);
}

// ================= HMMA GEMM, fp16 2-product ===============================
#define GKC  64
#define LDSR 72
#define GEMM_SMEM (3 * 128 * LDSR * 2)   // 55296 B

__global__ void __launch_bounds__(256, 2)
gemm_fp16_kernel(int a_sel, float* __restrict__ outPlain)
{
    extern __shared__ __half ds[];
    __half* sAh = ds;
    __half* sAl = ds + 9216;
    __half* sBf = ds + 18432;

    const int tid  = threadIdx.x;
    const int wid  = tid >> 5;
    const int lane = tid & 31;
    const int wm   = wid >> 2;
    const int wn   = wid & 3;

    const int m0 = blockIdx.y * 128;
    const int n0 = blockIdx.x * 128;

    const __half* Ah = a_sel ? g_Ofh : g_Xh;
    const __half* Al = a_sel ? g_Ofl : g_Xl;
    const int slot = a_sel ? 3 : (int)blockIdx.z;
    const __half* Wf = g_Wf + ((size_t)slot << 20);

    float* dstF = (slot == 0) ? g_Q : g_K;
    const int isV = (slot == 2);

    const uint32_t aAh = smem_u32(sAh);
    const uint32_t aAl = aAh + 18432;
    const uint32_t aBf = aAh + 36864;

    const int rA   = wm * 64 + (lane & 7) + ((lane >> 3) & 1) * 8;
    const int cA   = ((lane >> 4) & 1) * 8;
    const int rowB = (lane & 7) + ((lane >> 4) & 1) * 8;
    const int colB = ((lane >> 3) & 1) * 8;

    float acc[4][4][4];
#pragma unroll
    for (int i = 0; i < 4; i++)
#pragma unroll
        for (int j = 0; j < 4; j++)
#pragma unroll
            for (int q = 0; q < 4; q++) acc[i][j][q] = 0.0f;

    for (int ch = 0; ch < D_MODEL / GKC; ch++) {
        const int k0 = ch * GKC;
        __syncthreads();
#pragma unroll
        for (int p = 0; p < 4; p++) {
            int g  = tid + p * 256;
            int r  = g >> 3;
            int c8 = (g & 7) * 8;
            int so = r * LDSR + c8;
            *(uint4*)(sAh + so) = *(const uint4*)(Ah + (size_t)(m0 + r) * D_MODEL + k0 + c8);
            *(uint4*)(sAl + so) = *(const uint4*)(Al + (size_t)(m0 + r) * D_MODEL + k0 + c8);
            *(uint4*)(sBf + so) = *(const uint4*)(Wf + (size_t)(n0 + r) * D_MODEL + k0 + c8);
        }
        __syncthreads();

#pragma unroll
        for (int ks = 0; ks < 4; ks++) {
            uint32_t ah[4][4], al[4][4];
#pragma unroll
            for (int i = 0; i < 4; i++) {
                uint32_t off = (uint32_t)((rA + i * 16) * LDSR + ks * 16 + cA) * 2;
                ldsm_x4(ah[i], aAh + off);
                ldsm_x4(al[i], aAl + off);
            }
#pragma unroll
            for (int jp = 0; jp < 2; jp++) {
                uint32_t bf4[4];
                uint32_t off = (uint32_t)((wn * 32 + jp * 16 + rowB) * LDSR
                                          + ks * 16 + colB) * 2;
                ldsm_x4(bf4, aBf + off);
#pragma unroll
                for (int i = 0; i < 4; i++) {
                    mma16816h(acc[i][2 * jp],     ah[i], bf4[0], bf4[1]);
                    mma16816h(acc[i][2 * jp],     al[i], bf4[0], bf4[1]);
                    mma16816h(acc[i][2 * jp + 1], ah[i], bf4[2], bf4[3]);
                    mma16816h(acc[i][2 * jp + 1], al[i], bf4[2], bf4[3]);
                }
            }
        }
    }

#pragma unroll
    for (int i = 0; i < 4; i++) {
#pragma unroll
        for (int j = 0; j < 4; j++) {
            int R0 = m0 + wm * 64 + i * 16 + (lane >> 2);
            int C  = n0 + wn * 32 + j * 8 + (lane & 3) * 2;
            if (a_sel == 0) {
                int hh = C >> 6, d = C & 63;
#pragma unroll
                for (int half = 0; half < 2; half++) {
                    int R = R0 + half * 8;
                    int b = R >> 11, t = R & 2047;
                    size_t o = ((size_t)(b * N_HEADS + hh) * SEQ + t) * HEAD_DIM + d;
                    float v0 = acc[i][j][half * 2], v1 = acc[i][j][half * 2 + 1];
                    if (isV) {
                        __half2 vh = __floats2half2_rn(v0, v1);
                        *(__half2*)(g_Vf + o) = vh;
                    } else {
                        *(float2*)(dstF + o) = make_float2(v0, v1);
                    }
                }
            } else {
#pragma unroll
                for (int half = 0; half < 2; half++) {
                    int R = R0 + half * 8;
                    *(float2*)(outPlain + (size_t)R * D_MODEL + C) =
                        make_float2(acc[i][j][half * 2], acc[i][j][half * 2 + 1]);
                }
            }
        }
    }
}

// ---------------- RoPE: Q -> fp16 (scale 0.125*log2e), K -> fp16 -----------
__global__ void __launch_bounds__(256)
rope_split_kernel()
{
    int idx = blockIdx.x * blockDim.x + threadIdx.x;
    int d  = idx & 31;
    int t  = (idx >> 5) & (SEQ - 1);
    int bh = idx >> 16;

    float inv_freq = expf(-(float)d * 0.28782313662425573f);
    float ang = (float)t * inv_freq;
    float s, c;
    sincosf(ang, &s, &c);

    const float QS = 0.18033688011112042f;   // 0.125 * log2(e)
    size_t base = ((size_t)bh * SEQ + t) * HEAD_DIM + d;
    float q1 = g_Q[base], q2 = g_Q[base + 32];
    float qa = (q1 * c - q2 * s) * QS;
    float qb = (q2 * c + q1 * s) * QS;
    float k1 = g_K[base], k2 = g_K[base + 32];
    float ka = k1 * c - k2 * s;
    float kb = k2 * c + k1 * s;

    g_Q16[base]      = __float2half_rn(qa);
    g_Q16[base + 32] = __float2half_rn(qb);
    g_K16[base]      = __float2half_rn(ka);
    g_K16[base + 32] = __float2half_rn(kb);
}

// ---------------- Flash attention (causal, base-2 softmax) -------------------
// QK^T: single fp16 product. P·V: single fp16 product.
// Row-sum l computed BY THE TENSOR CORE via a ones-column appended to V
// (V smem stride 72 leaves cols 64..71 free; col 64 = 1, 65..71 = 0).
// accS (the ones-column accumulator) is rescaled with accO each iteration,
// so at the end accS == l exactly (summed from the same rounded P).
#define FLD 72
#define QBYTES   18432u                // Q fp16 [128][72]
#define KVTILE_B 9216u                 // one of Kf/Vf [64][72] fp16
#define KVSTG_B  18432u                // 2 tiles
#define FA_SMEM  (QBYTES + 2 * KVSTG_B)   // 55296 B

__global__ void __launch_bounds__(256, 2)
flash_mma_kernel()
{
    extern __shared__ __half sbh[];
    const uint32_t aQf = smem_u32(sbh);

    const int tid  = threadIdx.x;
    const int wid  = tid >> 5;
    const int lane = tid & 31;
    const int it   = (int)gridDim.x - 1 - (int)blockIdx.x;   // heavy first
    const int bh   = blockIdx.y;
    const size_t base = (size_t)bh * SEQ * HEAD_DIM;

    const int kr0 = tid >> 3,          kc0 = (tid & 7) * 8;
    const int kr1 = (tid + 256) >> 3,  kc1 = ((tid + 256) & 7) * 8;
    auto load_kv = [&](int jt, int stg) {
        const size_t kb = base + (size_t)jt * 64 * 64;
        const uint32_t sbase = aQf + QBYTES + (uint32_t)stg * KVSTG_B;
#pragma unroll
        for (int p = 0; p < 4; p++) {
            const int tile = p >> 1;                  // 0 = Kf, 1 = Vf
            const int r = (p & 1) ? kr1 : kr0;
            const int c = (p & 1) ? kc1 : kc0;
            uint32_t dst = sbase + (uint32_t)tile * KVTILE_B
                         + (uint32_t)(r * FLD + c) * 2;
            const __half* src = (tile == 0) ? (g_K16 + kb + r * 64 + c)
                                            : (g_Vf  + kb + r * 64 + c);
            cp16(dst, src);
        }
        CP_COMMIT();
    };

    load_kv(0, 0);

    // ---- load Q; init V pad columns (col 64 = 1, 65..71 = 0), both stages --
    {
        const __half* qf = g_Q16 + base + (size_t)it * 128 * 64;
#pragma unroll
        for (int p = 0; p < 4; p++) {
            int g = tid + p * 256;
            int r = g >> 3, c8 = (g & 7) * 8;
            *(uint4*)(sbh + r * FLD + c8) = *(const uint4*)(qf + r * 64 + c8);
        }
        if (tid < 128) {       // 2 stages x 64 rows
            int stg = tid >> 6, r = tid & 63;
            uint4* pad = (uint4*)(sbh + (QBYTES + stg * KVSTG_B + KVTILE_B) / 2
                                      + r * FLD + 64);
            *pad = make_uint4(0x00003C00u, 0u, 0u, 0u);   // {1,0,0,0,0,0,0,0} fp16
        }
    }
    __syncthreads();

    uint32_t qf[4][4];
    {
        int rAq = (lane & 7) + ((lane >> 3) & 1) * 8;
        int cAq = ((lane >> 4) & 1) * 8;
#pragma unroll
        for (int ks = 0; ks < 4; ks++) {
            uint32_t off = (uint32_t)((wid * 16 + rAq) * FLD + ks * 16 + cAq) * 2;
            ldsm_x4(qf[ks], aQf + off);
        }
    }

    float accO[8][4];
    float accS[4] = {0.0f, 0.0f, 0.0f, 0.0f};   // ones-column = row sums
#pragma unroll
    for (int j = 0; j < 8; j++)
#pragma unroll
        for (int q = 0; q < 4; q++) accO[j][q] = 0.0f;
    float m0 = -1e30f, m1 = -1e30f;

    const int rowK = (lane & 7) + ((lane >> 4) & 1) * 8;
    const int colK = ((lane >> 3) & 1) * 8;
    const int rowV = (lane & 15);
    const int colV = (lane >> 4) * 8;
    const int rowS = (lane & 15);               // ldsm_x2 rows (lanes 0-15)

    const int jt_end = 2 * it + 1;
    for (int jt = 0; jt <= jt_end; jt++) {
        const int stg = jt & 1;
        if (jt < jt_end) { load_kv(jt + 1, stg ^ 1); CP_WAIT1(); }
        else             { CP_WAIT0(); }
        __syncthreads();

        const uint32_t aKf = aQf + QBYTES + (uint32_t)stg * KVSTG_B;
        const uint32_t aVf = aKf + KVTILE_B;

        float s[8][4];
#pragma unroll
        for (int j = 0; j < 8; j++)
#pragma unroll
            for (int q = 0; q < 4; q++) s[j][q] = 0.0f;

        // ---- S = Q @ K^T  (single fp16 product) ----
#pragma unroll
        for (int ks = 0; ks < 4; ks++) {
#pragma unroll
            for (int pr = 0; pr < 4; pr++) {
                uint32_t kf4[4];
                uint32_t off = (uint32_t)((pr * 16 + rowK) * FLD + ks * 16 + colK) * 2;
                ldsm_x4(kf4, aKf + off);
                mma16816h(s[2 * pr],     qf[ks], kf4[0], kf4[1]);
                mma16816h(s[2 * pr + 1], qf[ks], kf4[2], kf4[3]);
            }
        }

        if (jt >= 2 * it) {
            int row0 = it * 128 + wid * 16 + (lane >> 2);
#pragma unroll
            for (int j = 0; j < 8; j++) {
                int col = jt * 64 + j * 8 + (lane & 3) * 2;
                if (col     > row0)     s[j][0] = -1e30f;
                if (col + 1 > row0)     s[j][1] = -1e30f;
                if (col     > row0 + 8) s[j][2] = -1e30f;
                if (col + 1 > row0 + 8) s[j][3] = -1e30f;
            }
        }

        // ---- online softmax (base-2); P -> fp16; no scalar row-sum ----
        float mx0 = -1e30f, mx1 = -1e30f;
#pragma unroll
        for (int j = 0; j < 8; j++) {
            mx0 = fmaxf(mx0, fmaxf(s[j][0], s[j][1]));
            mx1 = fmaxf(mx1, fmaxf(s[j][2], s[j][3]));
        }
        mx0 = fmaxf(mx0, __shfl_xor_sync(0xffffffffu, mx0, 1));
        mx0 = fmaxf(mx0, __shfl_xor_sync(0xffffffffu, mx0, 2));
        mx1 = fmaxf(mx1, __shfl_xor_sync(0xffffffffu, mx1, 1));
        mx1 = fmaxf(mx1, __shfl_xor_sync(0xffffffffu, mx1, 2));
        float m0n = fmaxf(m0, mx0), m1n = fmaxf(m1, mx1);
        float r0 = exp2f(m0 - m0n);
        float r1 = exp2f(m1 - m1n);
        m0 = m0n; m1 = m1n;

        uint32_t parr[8][2];
#pragma unroll
        for (int j = 0; j < 8; j++) {
            __half2 p01 = __floats2half2_rn(exp2f(s[j][0] - m0n),
                                            exp2f(s[j][1] - m0n));
            __half2 p23 = __floats2half2_rn(exp2f(s[j][2] - m1n),
                                            exp2f(s[j][3] - m1n));
            parr[j][0] = *(uint32_t*)&p01;
            parr[j][1] = *(uint32_t*)&p23;
        }
#pragma unroll
        for (int j = 0; j < 8; j++) {
            accO[j][0] *= r0; accO[j][1] *= r0;
            accO[j][2] *= r1; accO[j][3] *= r1;
        }
        accS[0] *= r0; accS[1] *= r0;
        accS[2] *= r1; accS[3] *= r1;

        // ---- O += P @ V ; accS += P @ ones ----
#pragma unroll
        for (int ks = 0; ks < 4; ks++) {
            uint32_t ph[4] = { parr[2 * ks][0], parr[2 * ks][1],
                               parr[2 * ks + 1][0], parr[2 * ks + 1][1] };
#pragma unroll
            for (int dp = 0; dp < 4; dp++) {
                uint32_t vf4[4];
                uint32_t off = (uint32_t)((ks * 16 + rowV) * FLD + dp * 16 + colV) * 2;
                ldsm_x4_t(vf4, aVf + off);
                mma16816h(accO[2 * dp],     ph, vf4[0], vf4[1]);
                mma16816h(accO[2 * dp + 1], ph, vf4[2], vf4[3]);
            }
            uint32_t on2[2];
            ldsm_x2_t(on2, aVf + (uint32_t)((ks * 16 + rowS) * FLD + 64) * 2);
            mma16816h(accS, ph, on2[0], on2[1]);
        }
        __syncthreads();
    }

    // ---- epilogue: l from accS (ones column, col-0 lanes), O / l ----
    float sum0 = __shfl_sync(0xffffffffu, accS[0], lane & 28);
    float sum1 = __shfl_sync(0xffffffffu, accS[2], lane & 28);
    float i0 = 1.0f / sum0, i1 = 1.0f / sum1;
    const int b = bh >> 4, hh = bh & 15;
    const int t0 = it * 128 + wid * 16 + (lane >> 2);
#pragma unroll
    for (int j = 0; j < 8; j++) {
        int d = hh * 64 + j * 8 + (lane & 3) * 2;
        size_t o0 = (size_t)(b * SEQ + t0) * D_MODEL + d;
        size_t o1 = (size_t)(b * SEQ + t0 + 8) * D_MODEL + d;
        uint32_t hi, lo;
        split2h(accO[j][0] * i0, accO[j][1] * i0, hi, lo);
        *(uint32_t*)(g_Ofh + o0) = hi;
        *(uint32_t*)(g_Ofl + o0) = lo;
        split2h(accO[j][2] * i1, accO[j][3] * i1, hi, lo);
        *(uint32_t*)(g_Ofh + o1) = hi;
        *(uint32_t*)(g_Ofl + o1) = lo;
    }
}

// ---------------- launch ----------------------------------------------------
extern "C" void kernel_launch(void* const* d_in, const int* in_sizes, int n_in,
                              void* d_out, int out_size)
{
    const float* x  = (const float*)d_in[0];
    const float* Wq = (const float*)d_in[1];
    const float* Wk = (const float*)d_in[2];
    const float* Wv = (const float*)d_in[3];
    const float* Wo = (const float*)d_in[4];
    float* out = (float*)d_out;

    cudaFuncSetAttribute(gemm_fp16_kernel,
                         cudaFuncAttributeMaxDynamicSharedMemorySize, GEMM_SMEM);
    cudaFuncSetAttribute(flash_mma_kernel,
                         cudaFuncAttributeMaxDynamicSharedMemorySize, FA_SMEM);

    // 0) pre-split inputs to fp16
    split_x_kernel<<<NELEM / 4 / 256, 256>>>(x);
    split_w_kernel<<<(4 * 1024 * 1024) / 4 / 256, 256>>>(Wq, Wk, Wv, Wo);

    // 1) fused QKV projections (grid.z selects weight slot)
    dim3 gq(D_MODEL / 128, M_ROWS / 128, 3);
    gemm_fp16_kernel<<<gq, 256, GEMM_SMEM>>>(0, nullptr);

    // 2) RoPE: Q -> fp16 (x 0.125*log2e), K -> fp16
    rope_split_kernel<<<(BATCH * N_HEADS * SEQ * 32) / 256, 256>>>();

    // 3) causal flash attention (fp16 HMMA, tensor-core row sums)
    flash_mma_kernel<<<dim3(SEQ / 128, BATCH * N_HEADS), 256, FA_SMEM>>>();

    // 4) output projection: out = O @ Wo^T
    dim3 go(D_MODEL / 128, M_ROWS / 128, 1);
    gemm_fp16_kernel<<<go, 256, GEMM_SMEM>>>(1, out);
}

// round 16
// speedup vs baseline: 1.7192x; 1.0030x over previous
#include <cuda_runtime.h>
#include <cuda_bf16.h>
#include <cuda_fp16.h>
#include <math.h>
#include <stdint.h>

#define D_MODEL  1024
#define N_HEADS  16
#define HEAD_DIM 64
#define BATCH    4
#define SEQ      2048
#define M_ROWS   (BATCH * SEQ)   // 8192
#define NELEM    (BATCH * N_HEADS * SEQ * HEAD_DIM)   // 8388608

// ---------------- scratch (static device arrays; no allocation allowed) ----
__device__ float g_Q[NELEM];                 // [B,H,T,Dh] fp32 (pre-rope)
__device__ float g_K[NELEM];
__device__ __half g_Xh[NELEM], g_Xl[NELEM];              // x fp16 hi/lo
__device__ __half g_Wf[4 * 1024 * 1024];                 // W single fp16 (q,k,v,o)
__device__ __half g_Q16[NELEM];                          // post-rope Q fp16
__device__ __half g_K16[NELEM];                          // K single fp16
__device__ __half g_Vf[NELEM];                           // V single fp16
__device__ __half g_Ofh[NELEM], g_Ofl[NELEM];            // attn out fp16 hi/lo

// ================= helpers =================================================
__device__ __forceinline__ uint32_t smem_u32(const void* p) {
    uint32_t a;
    asm("{ .reg .u64 t; cvta.to.shared.u64 t, %1; cvt.u32.u64 %0, t; }"
        : "=r"(a) : "l"(p));
    return a;
}
__device__ __forceinline__ void ldsm_x4(uint32_t* r, uint32_t a) {
    asm volatile("ldmatrix.sync.aligned.m8n8.x4.shared.b16 {%0,%1,%2,%3}, [%4];"
                 : "=r"(r[0]), "=r"(r[1]), "=r"(r[2]), "=r"(r[3]) : "r"(a));
}
__device__ __forceinline__ void ldsm_x4_t(uint32_t* r, uint32_t a) {
    asm volatile("ldmatrix.sync.aligned.m8n8.x4.trans.shared.b16 {%0,%1,%2,%3}, [%4];"
                 : "=r"(r[0]), "=r"(r[1]), "=r"(r[2]), "=r"(r[3]) : "r"(a));
}
__device__ __forceinline__ void ldsm_x2_t(uint32_t* r, uint32_t a) {
    asm volatile("ldmatrix.sync.aligned.m8n8.x2.trans.shared.b16 {%0,%1}, [%2];"
                 : "=r"(r[0]), "=r"(r[1]) : "r"(a));
}
__device__ __forceinline__ void mma16816h(float* c, const uint32_t* a,
                                          uint32_t b0, uint32_t b1) {
    asm volatile("mma.sync.aligned.m16n8k16.row.col.f32.f16.f16.f32 "
                 "{%0,%1,%2,%3}, {%4,%5,%6,%7}, {%8,%9}, {%0,%1,%2,%3};"
                 : "+f"(c[0]), "+f"(c[1]), "+f"(c[2]), "+f"(c[3])
                 : "r"(a[0]), "r"(a[1]), "r"(a[2]), "r"(a[3]),
                   "r"(b0), "r"(b1));
}
__device__ __forceinline__ void cp16(uint32_t dst, const void* src) {
    asm volatile("cp.async.cg.shared.global [%0], [%1], 16;"
                 :: "r"(dst), "l"(src));
}
#define CP_COMMIT() asm volatile("cp.async.commit_group;" ::: "memory")
#define CP_WAIT0()  asm volatile("cp.async.wait_group 0;" ::: "memory")
#define CP_WAIT1()  asm volatile("cp.async.wait_group 1;" ::: "memory")

__device__ __forceinline__ void split2h(float x, float y,
                                        uint32_t& hi, uint32_t& lo) {
    __half2 h = __floats2half2_rn(x, y);
    hi = *(uint32_t*)&h;
    __half2 l = __floats2half2_rn(x - __half2float(h.x),
                                  y - __half2float(h.y));
    lo = *(uint32_t*)&l;
}

// ================= one-shot split kernels ==================================
__global__ void __launch_bounds__(256)
split_x_kernel(const float* __restrict__ x)
{
    int i = blockIdx.x * 256 + threadIdx.x;
    float4 v = ((const float4*)x)[i];
    size_t o = (size_t)i * 4;
    uint32_t h0, l0, h1, l1;
    split2h(v.x, v.y, h0, l0);
    split2h(v.z, v.w, h1, l1);
    *(uint2*)(g_Xh + o) = make_uint2(h0, h1);
    *(uint2*)(g_Xl + o) = make_uint2(l0, l1);
}

__global__ void __launch_bounds__(256)
split_w_kernel(const float* __restrict__ Wq, const float* __restrict__ Wk,
               const float* __restrict__ Wv, const float* __restrict__ Wo)
{
    int i = blockIdx.x * 256 + threadIdx.x;
    int s = i >> 18;
    const float* src = (s == 0) ? Wq : (s == 1) ? Wk : (s == 2) ? Wv : Wo;
    float4 v = ((const float4*)src)[i & 0x3FFFF];
    size_t o = (size_t)i * 4;
    __half2 a = __floats2half2_rn(v.x, v.y);
    __half2 b = __floats2half2_rn(v.z, v.w);
    *(uint2*)(g_Wf + o) = make_uint2(*(uint32_t*)&a, *(uint32_t*)&b);
}

// ================= HMMA GEMM, fp16 2-product ===============================
#define GKC  64
#define LDSR 72
#define GEMM_SMEM (3 * 128 * LDSR * 2)   // 55296 B

__global__ void __launch_bounds__(256, 2)
gemm_fp16_kernel(int a_sel, float* __restrict__ outPlain)
{
    extern __shared__ __half ds[];
    __half* sAh = ds;
    __half* sAl = ds + 9216;
    __half* sBf = ds + 18432;

    const int tid  = threadIdx.x;
    const int wid  = tid >> 5;
    const int lane = tid & 31;
    const int wm   = wid >> 2;
    const int wn   = wid & 3;

    const int m0 = blockIdx.y * 128;
    const int n0 = blockIdx.x * 128;

    const __half* Ah = a_sel ? g_Ofh : g_Xh;
    const __half* Al = a_sel ? g_Ofl : g_Xl;
    const int slot = a_sel ? 3 : (int)blockIdx.z;
    const __half* Wf = g_Wf + ((size_t)slot << 20);

    float* dstF = (slot == 0) ? g_Q : g_K;
    const int isV = (slot == 2);

    const uint32_t aAh = smem_u32(sAh);
    const uint32_t aAl = aAh + 18432;
    const uint32_t aBf = aAh + 36864;

    const int rA   = wm * 64 + (lane & 7) + ((lane >> 3) & 1) * 8;
    const int cA   = ((lane >> 4) & 1) * 8;
    const int rowB = (lane & 7) + ((lane >> 4) & 1) * 8;
    const int colB = ((lane >> 3) & 1) * 8;

    float acc[4][4][4];
#pragma unroll
    for (int i = 0; i < 4; i++)
#pragma unroll
        for (int j = 0; j < 4; j++)
#pragma unroll
            for (int q = 0; q < 4; q++) acc[i][j][q] = 0.0f;

    for (int ch = 0; ch < D_MODEL / GKC; ch++) {
        const int k0 = ch * GKC;
        __syncthreads();
#pragma unroll
        for (int p = 0; p < 4; p++) {
            int g  = tid + p * 256;
            int r  = g >> 3;
            int c8 = (g & 7) * 8;
            int so = r * LDSR + c8;
            *(uint4*)(sAh + so) = *(const uint4*)(Ah + (size_t)(m0 + r) * D_MODEL + k0 + c8);
            *(uint4*)(sAl + so) = *(const uint4*)(Al + (size_t)(m0 + r) * D_MODEL + k0 + c8);
            *(uint4*)(sBf + so) = *(const uint4*)(Wf + (size_t)(n0 + r) * D_MODEL + k0 + c8);
        }
        __syncthreads();

#pragma unroll
        for (int ks = 0; ks < 4; ks++) {
            uint32_t ah[4][4], al[4][4];
#pragma unroll
            for (int i = 0; i < 4; i++) {
                uint32_t off = (uint32_t)((rA + i * 16) * LDSR + ks * 16 + cA) * 2;
                ldsm_x4(ah[i], aAh + off);
                ldsm_x4(al[i], aAl + off);
            }
#pragma unroll
            for (int jp = 0; jp < 2; jp++) {
                uint32_t bf4[4];
                uint32_t off = (uint32_t)((wn * 32 + jp * 16 + rowB) * LDSR
                                          + ks * 16 + colB) * 2;
                ldsm_x4(bf4, aBf + off);
#pragma unroll
                for (int i = 0; i < 4; i++) {
                    mma16816h(acc[i][2 * jp],     ah[i], bf4[0], bf4[1]);
                    mma16816h(acc[i][2 * jp],     al[i], bf4[0], bf4[1]);
                    mma16816h(acc[i][2 * jp + 1], ah[i], bf4[2], bf4[3]);
                    mma16816h(acc[i][2 * jp + 1], al[i], bf4[2], bf4[3]);
                }
            }
        }
    }

#pragma unroll
    for (int i = 0; i < 4; i++) {
#pragma unroll
        for (int j = 0; j < 4; j++) {
            int R0 = m0 + wm * 64 + i * 16 + (lane >> 2);
            int C  = n0 + wn * 32 + j * 8 + (lane & 3) * 2;
            if (a_sel == 0) {
                int hh = C >> 6, d = C & 63;
#pragma unroll
                for (int half = 0; half < 2; half++) {
                    int R = R0 + half * 8;
                    int b = R >> 11, t = R & 2047;
                    size_t o = ((size_t)(b * N_HEADS + hh) * SEQ + t) * HEAD_DIM + d;
                    float v0 = acc[i][j][half * 2], v1 = acc[i][j][half * 2 + 1];
                    if (isV) {
                        __half2 vh = __floats2half2_rn(v0, v1);
                        *(__half2*)(g_Vf + o) = vh;
                    } else {
                        *(float2*)(dstF + o) = make_float2(v0, v1);
                    }
                }
            } else {
#pragma unroll
                for (int half = 0; half < 2; half++) {
                    int R = R0 + half * 8;
                    *(float2*)(outPlain + (size_t)R * D_MODEL + C) =
                        make_float2(acc[i][j][half * 2], acc[i][j][half * 2 + 1]);
                }
            }
        }
    }
}

// ---------------- RoPE: Q -> fp16 (scale 0.125*log2e), K -> fp16 -----------
__global__ void __launch_bounds__(256)
rope_split_kernel()
{
    int idx = blockIdx.x * blockDim.x + threadIdx.x;
    int d  = idx & 31;
    int t  = (idx >> 5) & (SEQ - 1);
    int bh = idx >> 16;

    float inv_freq = expf(-(float)d * 0.28782313662425573f);
    float ang = (float)t * inv_freq;
    float s, c;
    sincosf(ang, &s, &c);

    const float QS = 0.18033688011112042f;   // 0.125 * log2(e)
    size_t base = ((size_t)bh * SEQ + t) * HEAD_DIM + d;
    float q1 = g_Q[base], q2 = g_Q[base + 32];
    float qa = (q1 * c - q2 * s) * QS;
    float qb = (q2 * c + q1 * s) * QS;
    float k1 = g_K[base], k2 = g_K[base + 32];
    float ka = k1 * c - k2 * s;
    float kb = k2 * c + k1 * s;

    g_Q16[base]      = __float2half_rn(qa);
    g_Q16[base + 32] = __float2half_rn(qb);
    g_K16[base]      = __float2half_rn(ka);
    g_K16[base + 32] = __float2half_rn(kb);
}

// ---------------- Flash attention (causal, base-2 softmax) -------------------
// 3-stage cp.async KV pipeline, ONE __syncthreads per KV tile.
// Per iter: wait(stage jt) -> barrier -> issue load(jt+2) -> compute.
// Stage overwritten by load(jt+2) was last read at jt-1, whose reads precede
// this barrier in every thread's program order -> safe with no tail barrier.
// Row-sum via ones-column appended to V (cols 64..71 of the stride-72 tile).
#define FLD 72
#define QBYTES   18432u                // Q fp16 [128][72]
#define KVTILE_B 9216u                 // one of Kf/Vf [64][72] fp16
#define KVSTG_B  18432u                // 2 tiles
#define FA_SMEM  (QBYTES + 3 * KVSTG_B)   // 73728 B

__global__ void __launch_bounds__(256, 2)
flash_mma_kernel()
{
    extern __shared__ __half sbh[];
    const uint32_t aQf = smem_u32(sbh);

    const int tid  = threadIdx.x;
    const int wid  = tid >> 5;
    const int lane = tid & 31;
    const int it   = (int)gridDim.x - 1 - (int)blockIdx.x;   // heavy first
    const int bh   = blockIdx.y;
    const size_t base = (size_t)bh * SEQ * HEAD_DIM;

    const int kr0 = tid >> 3,          kc0 = (tid & 7) * 8;
    const int kr1 = (tid + 256) >> 3,  kc1 = ((tid + 256) & 7) * 8;
    auto load_kv = [&](int jt, int stg) {
        const size_t kb = base + (size_t)jt * 64 * 64;
        const uint32_t sbase = aQf + QBYTES + (uint32_t)stg * KVSTG_B;
#pragma unroll
        for (int p = 0; p < 4; p++) {
            const int tile = p >> 1;                  // 0 = Kf, 1 = Vf
            const int r = (p & 1) ? kr1 : kr0;
            const int c = (p & 1) ? kc1 : kc0;
            uint32_t dst = sbase + (uint32_t)tile * KVTILE_B
                         + (uint32_t)(r * FLD + c) * 2;
            const __half* src = (tile == 0) ? (g_K16 + kb + r * 64 + c)
                                            : (g_Vf  + kb + r * 64 + c);
            cp16(dst, src);
        }
        CP_COMMIT();
    };

    const int jt_end = 2 * it + 1;
    load_kv(0, 0);
    if (jt_end >= 1) load_kv(1, 1); else CP_COMMIT();   // keep group count fixed

    // ---- load Q; init V pad columns (col 64 = 1, 65..71 = 0), 3 stages ----
    {
        const __half* qf = g_Q16 + base + (size_t)it * 128 * 64;
#pragma unroll
        for (int p = 0; p < 4; p++) {
            int g = tid + p * 256;
            int r = g >> 3, c8 = (g & 7) * 8;
            *(uint4*)(sbh + r * FLD + c8) = *(const uint4*)(qf + r * 64 + c8);
        }
        if (tid < 192) {       // 3 stages x 64 rows
            int stg = tid >> 6, r = tid & 63;
            uint4* pad = (uint4*)(sbh + (QBYTES + stg * KVSTG_B + KVTILE_B) / 2
                                      + r * FLD + 64);
            *pad = make_uint4(0x00003C00u, 0u, 0u, 0u);   // {1,0,...} fp16
        }
    }
    __syncthreads();     // Q + pads visible

    uint32_t qf[4][4];
    {
        int rAq = (lane & 7) + ((lane >> 3) & 1) * 8;
        int cAq = ((lane >> 4) & 1) * 8;
#pragma unroll
        for (int ks = 0; ks < 4; ks++) {
            uint32_t off = (uint32_t)((wid * 16 + rAq) * FLD + ks * 16 + cAq) * 2;
            ldsm_x4(qf[ks], aQf + off);
        }
    }

    float accO[8][4];
    float accS[4] = {0.0f, 0.0f, 0.0f, 0.0f};   // ones-column = row sums
#pragma unroll
    for (int j = 0; j < 8; j++)
#pragma unroll
        for (int q = 0; q < 4; q++) accO[j][q] = 0.0f;
    float m0 = -1e30f, m1 = -1e30f;

    const int rowK = (lane & 7) + ((lane >> 4) & 1) * 8;
    const int colK = ((lane >> 3) & 1) * 8;
    const int rowV = (lane & 15);
    const int colV = (lane >> 4) * 8;
    const int rowS = (lane & 15);

    int stg = 0;
    for (int jt = 0; jt <= jt_end; jt++) {
        if (jt < jt_end) { CP_WAIT1(); }
        else             { CP_WAIT0(); }
        __syncthreads();                          // stage jt ready; jt-1 reads done

        if (jt + 2 <= jt_end) {
            int lstg = stg + 2; if (lstg >= 3) lstg -= 3;
            load_kv(jt + 2, lstg);
        }

        const uint32_t aKf = aQf + QBYTES + (uint32_t)stg * KVSTG_B;
        const uint32_t aVf = aKf + KVTILE_B;

        float s[8][4];
#pragma unroll
        for (int j = 0; j < 8; j++)
#pragma unroll
            for (int q = 0; q < 4; q++) s[j][q] = 0.0f;

        // ---- S = Q @ K^T  (single fp16 product) ----
#pragma unroll
        for (int ks = 0; ks < 4; ks++) {
#pragma unroll
            for (int pr = 0; pr < 4; pr++) {
                uint32_t kf4[4];
                uint32_t off = (uint32_t)((pr * 16 + rowK) * FLD + ks * 16 + colK) * 2;
                ldsm_x4(kf4, aKf + off);
                mma16816h(s[2 * pr],     qf[ks], kf4[0], kf4[1]);
                mma16816h(s[2 * pr + 1], qf[ks], kf4[2], kf4[3]);
            }
        }

        if (jt >= 2 * it) {
            int row0 = it * 128 + wid * 16 + (lane >> 2);
#pragma unroll
            for (int j = 0; j < 8; j++) {
                int col = jt * 64 + j * 8 + (lane & 3) * 2;
                if (col     > row0)     s[j][0] = -1e30f;
                if (col + 1 > row0)     s[j][1] = -1e30f;
                if (col     > row0 + 8) s[j][2] = -1e30f;
                if (col + 1 > row0 + 8) s[j][3] = -1e30f;
            }
        }

        // ---- online softmax (base-2); P -> fp16 ----
        float mx0 = -1e30f, mx1 = -1e30f;
#pragma unroll
        for (int j = 0; j < 8; j++) {
            mx0 = fmaxf(mx0, fmaxf(s[j][0], s[j][1]));
            mx1 = fmaxf(mx1, fmaxf(s[j][2], s[j][3]));
        }
        mx0 = fmaxf(mx0, __shfl_xor_sync(0xffffffffu, mx0, 1));
        mx0 = fmaxf(mx0, __shfl_xor_sync(0xffffffffu, mx0, 2));
        mx1 = fmaxf(mx1, __shfl_xor_sync(0xffffffffu, mx1, 1));
        mx1 = fmaxf(mx1, __shfl_xor_sync(0xffffffffu, mx1, 2));
        float m0n = fmaxf(m0, mx0), m1n = fmaxf(m1, mx1);
        float r0 = exp2f(m0 - m0n);
        float r1 = exp2f(m1 - m1n);
        m0 = m0n; m1 = m1n;

        uint32_t parr[8][2];
#pragma unroll
        for (int j = 0; j < 8; j++) {
            __half2 p01 = __floats2half2_rn(exp2f(s[j][0] - m0n),
                                            exp2f(s[j][1] - m0n));
            __half2 p23 = __floats2half2_rn(exp2f(s[j][2] - m1n),
                                            exp2f(s[j][3] - m1n));
            parr[j][0] = *(uint32_t*)&p01;
            parr[j][1] = *(uint32_t*)&p23;
        }
#pragma unroll
        for (int j = 0; j < 8; j++) {
            accO[j][0] *= r0; accO[j][1] *= r0;
            accO[j][2] *= r1; accO[j][3] *= r1;
        }
        accS[0] *= r0; accS[1] *= r0;
        accS[2] *= r1; accS[3] *= r1;

        // ---- O += P @ V ; accS += P @ ones ----
#pragma unroll
        for (int ks = 0; ks < 4; ks++) {
            uint32_t ph[4] = { parr[2 * ks][0], parr[2 * ks][1],
                               parr[2 * ks + 1][0], parr[2 * ks + 1][1] };
#pragma unroll
            for (int dp = 0; dp < 4; dp++) {
                uint32_t vf4[4];
                uint32_t off = (uint32_t)((ks * 16 + rowV) * FLD + dp * 16 + colV) * 2;
                ldsm_x4_t(vf4, aVf + off);
                mma16816h(accO[2 * dp],     ph, vf4[0], vf4[1]);
                mma16816h(accO[2 * dp + 1], ph, vf4[2], vf4[3]);
            }
            uint32_t on2[2];
            ldsm_x2_t(on2, aVf + (uint32_t)((ks * 16 + rowS) * FLD + 64) * 2);
            mma16816h(accS, ph, on2[0], on2[1]);
        }

        stg++; if (stg >= 3) stg = 0;
    }

    // ---- epilogue: l from accS (ones column, col-0 lanes), O / l ----
    float sum0 = __shfl_sync(0xffffffffu, accS[0], lane & 28);
    float sum1 = __shfl_sync(0xffffffffu, accS[2], lane & 28);
    float i0 = 1.0f / sum0, i1 = 1.0f / sum1;
    const int b = bh >> 4, hh = bh & 15;
    const int t0 = it * 128 + wid * 16 + (lane >> 2);
#pragma unroll
    for (int j = 0; j < 8; j++) {
        int d = hh * 64 + j * 8 + (lane & 3) * 2;
        size_t o0 = (size_t)(b * SEQ + t0) * D_MODEL + d;
        size_t o1 = (size_t)(b * SEQ + t0 + 8) * D_MODEL + d;
        uint32_t hi, lo;
        split2h(accO[j][0] * i0, accO[j][1] * i0, hi, lo);
        *(uint32_t*)(g_Ofh + o0) = hi;
        *(uint32_t*)(g_Ofl + o0) = lo;
        split2h(accO[j][2] * i1, accO[j][3] * i1, hi, lo);
        *(uint32_t*)(g_Ofh + o1) = hi;
        *(uint32_t*)(g_Ofl + o1) = lo;
    }
}

// ---------------- launch ----------------------------------------------------
extern "C" void kernel_launch(void* const* d_in, const int* in_sizes, int n_in,
                              void* d_out, int out_size)
{
    const float* x  = (const float*)d_in[0];
    const float* Wq = (const float*)d_in[1];
    const float* Wk = (const float*)d_in[2];
    const float* Wv = (const float*)d_in[3];
    const float* Wo = (const float*)d_in[4];
    float* out = (float*)d_out;

    cudaFuncSetAttribute(gemm_fp16_kernel,
                         cudaFuncAttributeMaxDynamicSharedMemorySize, GEMM_SMEM);
    cudaFuncSetAttribute(flash_mma_kernel,
                         cudaFuncAttributeMaxDynamicSharedMemorySize, FA_SMEM);

    // 0) pre-split inputs to fp16
    split_x_kernel<<<NELEM / 4 / 256, 256>>>(x);
    split_w_kernel<<<(4 * 1024 * 1024) / 4 / 256, 256>>>(Wq, Wk, Wv, Wo);

    // 1) fused QKV projections (grid.z selects weight slot)
    dim3 gq(D_MODEL / 128, M_ROWS / 128, 3);
    gemm_fp16_kernel<<<gq, 256, GEMM_SMEM>>>(0, nullptr);

    // 2) RoPE: Q -> fp16 (x 0.125*log2e), K -> fp16
    rope_split_kernel<<<(BATCH * N_HEADS * SEQ * 32) / 256, 256>>>();

    // 3) causal flash attention (fp16 HMMA, 3-stage pipeline, 1 barrier/iter)
    flash_mma_kernel<<<dim3(SEQ / 128, BATCH * N_HEADS), 256, FA_SMEM>>>();

    // 4) output projection: out = O @ Wo^T
    dim3 go(D_MODEL / 128, M_ROWS / 128, 1);
    gemm_fp16_kernel<<<go, 256, GEMM_SMEM>>>(1, out);
}

// round 17
// speedup vs baseline: 1.7275x; 1.0048x over previous
#include <cuda_runtime.h>
#include <cuda_bf16.h>
#include <cuda_fp16.h>
#include <math.h>
#include <stdint.h>

#define D_MODEL  1024
#define N_HEADS  16
#define HEAD_DIM 64
#define BATCH    4
#define SEQ      2048
#define M_ROWS   (BATCH * SEQ)   // 8192
#define NELEM    (BATCH * N_HEADS * SEQ * HEAD_DIM)   // 8388608

// ---------------- scratch (static device arrays; no allocation allowed) ----
__device__ float g_Q[NELEM];                 // [B,H,T,Dh] fp32 (pre-rope)
__device__ float g_K[NELEM];
__device__ __half g_Xh[NELEM], g_Xl[NELEM];              // x fp16 hi/lo
__device__ __half g_Wf[4 * 1024 * 1024];                 // W single fp16 (q,k,v,o)
__device__ __half g_Q16[NELEM];                          // post-rope Q fp16
__device__ __half g_K16[NELEM];                          // K single fp16
__device__ __half g_Vf[NELEM];                           // V single fp16
__device__ __half g_Ofh[NELEM], g_Ofl[NELEM];            // attn out fp16 hi/lo

// ================= helpers =================================================
__device__ __forceinline__ uint32_t smem_u32(const void* p) {
    uint32_t a;
    asm("{ .reg .u64 t; cvta.to.shared.u64 t, %1; cvt.u32.u64 %0, t; }"
        : "=r"(a) : "l"(p));
    return a;
}
__device__ __forceinline__ void ldsm_x4(uint32_t* r, uint32_t a) {
    asm volatile("ldmatrix.sync.aligned.m8n8.x4.shared.b16 {%0,%1,%2,%3}, [%4];"
                 : "=r"(r[0]), "=r"(r[1]), "=r"(r[2]), "=r"(r[3]) : "r"(a));
}
__device__ __forceinline__ void ldsm_x4_t(uint32_t* r, uint32_t a) {
    asm volatile("ldmatrix.sync.aligned.m8n8.x4.trans.shared.b16 {%0,%1,%2,%3}, [%4];"
                 : "=r"(r[0]), "=r"(r[1]), "=r"(r[2]), "=r"(r[3]) : "r"(a));
}
__device__ __forceinline__ void ldsm_x2_t(uint32_t* r, uint32_t a) {
    asm volatile("ldmatrix.sync.aligned.m8n8.x2.trans.shared.b16 {%0,%1}, [%2];"
                 : "=r"(r[0]), "=r"(r[1]) : "r"(a));
}
__device__ __forceinline__ void mma16816h(float* c, const uint32_t* a,
                                          uint32_t b0, uint32_t b1) {
    asm volatile("mma.sync.aligned.m16n8k16.row.col.f32.f16.f16.f32 "
                 "{%0,%1,%2,%3}, {%4,%5,%6,%7}, {%8,%9}, {%0,%1,%2,%3};"
                 : "+f"(c[0]), "+f"(c[1]), "+f"(c[2]), "+f"(c[3])
                 : "r"(a[0]), "r"(a[1]), "r"(a[2]), "r"(a[3]),
                   "r"(b0), "r"(b1));
}
__device__ __forceinline__ void cp16(uint32_t dst, const void* src) {
    asm volatile("cp.async.cg.shared.global [%0], [%1], 16;"
                 :: "r"(dst), "l"(src));
}
#define CP_COMMIT() asm volatile("cp.async.commit_group;" ::: "memory")
#define CP_WAIT0()  asm volatile("cp.async.wait_group 0;" ::: "memory")
#define CP_WAIT1()  asm volatile("cp.async.wait_group 1;" ::: "memory")

__device__ __forceinline__ void split2h(float x, float y,
                                        uint32_t& hi, uint32_t& lo) {
    __half2 h = __floats2half2_rn(x, y);
    hi = *(uint32_t*)&h;
    __half2 l = __floats2half2_rn(x - __half2float(h.x),
                                  y - __half2float(h.y));
    lo = *(uint32_t*)&l;
}

// ================= one-shot split kernel (x + all W merged) ================
// blocks [0, 8192)       : x -> g_Xh/g_Xl (fp16 hi/lo)
// blocks [8192, 12288)   : Wq/Wk/Wv/Wo -> g_Wf (single fp16)
__global__ void __launch_bounds__(256)
split_all_kernel(const float* __restrict__ x,
                 const float* __restrict__ Wq, const float* __restrict__ Wk,
                 const float* __restrict__ Wv, const float* __restrict__ Wo)
{
    int blk = blockIdx.x;
    if (blk < 8192) {
        int i = blk * 256 + threadIdx.x;
        float4 v = ((const float4*)x)[i];
        size_t o = (size_t)i * 4;
        uint32_t h0, l0, h1, l1;
        split2h(v.x, v.y, h0, l0);
        split2h(v.z, v.w, h1, l1);
        *(uint2*)(g_Xh + o) = make_uint2(h0, h1);
        *(uint2*)(g_Xl + o) = make_uint2(l0, l1);
    } else {
        int i = (blk - 8192) * 256 + threadIdx.x;    // < 1M float4s
        int s = i >> 18;
        const float* src = (s == 0) ? Wq : (s == 1) ? Wk : (s == 2) ? Wv : Wo;
        float4 v = ((const float4*)src)[i & 0x3FFFF];
        size_t o = (size_t)i * 4;
        __half2 a = __floats2half2_rn(v.x, v.y);
        __half2 b = __floats2half2_rn(v.z, v.w);
        *(uint2*)(g_Wf + o) = make_uint2(*(uint32_t*)&a, *(uint32_t*)&b);
    }
}

// ================= HMMA GEMM, fp16 2-product ===============================
#define GKC  64
#define LDSR 72
#define GEMM_SMEM (3 * 128 * LDSR * 2)   // 55296 B

__global__ void __launch_bounds__(256, 2)
gemm_fp16_kernel(int a_sel, float* __restrict__ outPlain)
{
    extern __shared__ __half ds[];
    __half* sAh = ds;
    __half* sAl = ds + 9216;
    __half* sBf = ds + 18432;

    const int tid  = threadIdx.x;
    const int wid  = tid >> 5;
    const int lane = tid & 31;
    const int wm   = wid >> 2;
    const int wn   = wid & 3;

    const int m0 = blockIdx.y * 128;
    const int n0 = blockIdx.x * 128;

    const __half* Ah = a_sel ? g_Ofh : g_Xh;
    const __half* Al = a_sel ? g_Ofl : g_Xl;
    const int slot = a_sel ? 3 : (int)blockIdx.z;
    const __half* Wf = g_Wf + ((size_t)slot << 20);

    float* dstF = (slot == 0) ? g_Q : g_K;
    const int isV = (slot == 2);

    const uint32_t aAh = smem_u32(sAh);
    const uint32_t aAl = aAh + 18432;
    const uint32_t aBf = aAh + 36864;

    const int rA   = wm * 64 + (lane & 7) + ((lane >> 3) & 1) * 8;
    const int cA   = ((lane >> 4) & 1) * 8;
    const int rowB = (lane & 7) + ((lane >> 4) & 1) * 8;
    const int colB = ((lane >> 3) & 1) * 8;

    float acc[4][4][4];
#pragma unroll
    for (int i = 0; i < 4; i++)
#pragma unroll
        for (int j = 0; j < 4; j++)
#pragma unroll
            for (int q = 0; q < 4; q++) acc[i][j][q] = 0.0f;

    for (int ch = 0; ch < D_MODEL / GKC; ch++) {
        const int k0 = ch * GKC;
        __syncthreads();
#pragma unroll
        for (int p = 0; p < 4; p++) {
            int g  = tid + p * 256;
            int r  = g >> 3;
            int c8 = (g & 7) * 8;
            int so = r * LDSR + c8;
            *(uint4*)(sAh + so) = *(const uint4*)(Ah + (size_t)(m0 + r) * D_MODEL + k0 + c8);
            *(uint4*)(sAl + so) = *(const uint4*)(Al + (size_t)(m0 + r) * D_MODEL + k0 + c8);
            *(uint4*)(sBf + so) = *(const uint4*)(Wf + (size_t)(n0 + r) * D_MODEL + k0 + c8);
        }
        __syncthreads();

#pragma unroll
        for (int ks = 0; ks < 4; ks++) {
            uint32_t ah[4][4], al[4][4];
#pragma unroll
            for (int i = 0; i < 4; i++) {
                uint32_t off = (uint32_t)((rA + i * 16) * LDSR + ks * 16 + cA) * 2;
                ldsm_x4(ah[i], aAh + off);
                ldsm_x4(al[i], aAl + off);
            }
#pragma unroll
            for (int jp = 0; jp < 2; jp++) {
                uint32_t bf4[4];
                uint32_t off = (uint32_t)((wn * 32 + jp * 16 + rowB) * LDSR
                                          + ks * 16 + colB) * 2;
                ldsm_x4(bf4, aBf + off);
#pragma unroll
                for (int i = 0; i < 4; i++) {
                    mma16816h(acc[i][2 * jp],     ah[i], bf4[0], bf4[1]);
                    mma16816h(acc[i][2 * jp],     al[i], bf4[0], bf4[1]);
                    mma16816h(acc[i][2 * jp + 1], ah[i], bf4[2], bf4[3]);
                    mma16816h(acc[i][2 * jp + 1], al[i], bf4[2], bf4[3]);
                }
            }
        }
    }

#pragma unroll
    for (int i = 0; i < 4; i++) {
#pragma unroll
        for (int j = 0; j < 4; j++) {
            int R0 = m0 + wm * 64 + i * 16 + (lane >> 2);
            int C  = n0 + wn * 32 + j * 8 + (lane & 3) * 2;
            if (a_sel == 0) {
                int hh = C >> 6, d = C & 63;
#pragma unroll
                for (int half = 0; half < 2; half++) {
                    int R = R0 + half * 8;
                    int b = R >> 11, t = R & 2047;
                    size_t o = ((size_t)(b * N_HEADS + hh) * SEQ + t) * HEAD_DIM + d;
                    float v0 = acc[i][j][half * 2], v1 = acc[i][j][half * 2 + 1];
                    if (isV) {
                        __half2 vh = __floats2half2_rn(v0, v1);
                        *(__half2*)(g_Vf + o) = vh;
                    } else {
                        *(float2*)(dstF + o) = make_float2(v0, v1);
                    }
                }
            } else {
#pragma unroll
                for (int half = 0; half < 2; half++) {
                    int R = R0 + half * 8;
                    *(float2*)(outPlain + (size_t)R * D_MODEL + C) =
                        make_float2(acc[i][j][half * 2], acc[i][j][half * 2 + 1]);
                }
            }
        }
    }
}

// ---------------- RoPE: Q -> fp16 (scale 0.125*log2e), K -> fp16 -----------
__global__ void __launch_bounds__(256)
rope_split_kernel()
{
    int idx = blockIdx.x * blockDim.x + threadIdx.x;
    int d  = idx & 31;
    int t  = (idx >> 5) & (SEQ - 1);
    int bh = idx >> 16;

    float inv_freq = expf(-(float)d * 0.28782313662425573f);
    float ang = (float)t * inv_freq;
    float s, c;
    sincosf(ang, &s, &c);

    const float QS = 0.18033688011112042f;   // 0.125 * log2(e)
    size_t base = ((size_t)bh * SEQ + t) * HEAD_DIM + d;
    float q1 = g_Q[base], q2 = g_Q[base + 32];
    float qa = (q1 * c - q2 * s) * QS;
    float qb = (q2 * c + q1 * s) * QS;
    float k1 = g_K[base], k2 = g_K[base + 32];
    float ka = k1 * c - k2 * s;
    float kb = k2 * c + k1 * s;

    g_Q16[base]      = __float2half_rn(qa);
    g_Q16[base + 32] = __float2half_rn(qb);
    g_K16[base]      = __float2half_rn(ka);
    g_K16[base + 32] = __float2half_rn(kb);
}

// ---------------- Flash attention (causal, base-2 softmax) -------------------
// 3-stage cp.async KV pipeline, one __syncthreads per KV tile.
// Row-sum via ones-column appended to V; the ones B-fragment is loop-invariant
// (all pad rows identical) so it is loaded ONCE before the mainloop.
#define FLD 72
#define QBYTES   18432u                // Q fp16 [128][72]
#define KVTILE_B 9216u                 // one of Kf/Vf [64][72] fp16
#define KVSTG_B  18432u                // 2 tiles
#define FA_SMEM  (QBYTES + 3 * KVSTG_B)   // 73728 B

__global__ void __launch_bounds__(256, 2)
flash_mma_kernel()
{
    extern __shared__ __half sbh[];
    const uint32_t aQf = smem_u32(sbh);

    const int tid  = threadIdx.x;
    const int wid  = tid >> 5;
    const int lane = tid & 31;
    const int it   = (int)gridDim.x - 1 - (int)blockIdx.x;   // heavy first
    const int bh   = blockIdx.y;
    const size_t base = (size_t)bh * SEQ * HEAD_DIM;

    const int kr0 = tid >> 3,          kc0 = (tid & 7) * 8;
    const int kr1 = (tid + 256) >> 3,  kc1 = ((tid + 256) & 7) * 8;
    auto load_kv = [&](int jt, int stg) {
        const size_t kb = base + (size_t)jt * 64 * 64;
        const uint32_t sbase = aQf + QBYTES + (uint32_t)stg * KVSTG_B;
#pragma unroll
        for (int p = 0; p < 4; p++) {
            const int tile = p >> 1;                  // 0 = Kf, 1 = Vf
            const int r = (p & 1) ? kr1 : kr0;
            const int c = (p & 1) ? kc1 : kc0;
            uint32_t dst = sbase + (uint32_t)tile * KVTILE_B
                         + (uint32_t)(r * FLD + c) * 2;
            const __half* src = (tile == 0) ? (g_K16 + kb + r * 64 + c)
                                            : (g_Vf  + kb + r * 64 + c);
            cp16(dst, src);
        }
        CP_COMMIT();
    };

    const int jt_end = 2 * it + 1;
    load_kv(0, 0);
    if (jt_end >= 1) load_kv(1, 1); else CP_COMMIT();   // keep group count fixed

    // ---- load Q; init V pad columns (col 64 = 1, 65..71 = 0), 3 stages ----
    {
        const __half* qf = g_Q16 + base + (size_t)it * 128 * 64;
#pragma unroll
        for (int p = 0; p < 4; p++) {
            int g = tid + p * 256;
            int r = g >> 3, c8 = (g & 7) * 8;
            *(uint4*)(sbh + r * FLD + c8) = *(const uint4*)(qf + r * 64 + c8);
        }
        if (tid < 192) {       // 3 stages x 64 rows
            int stg = tid >> 6, r = tid & 63;
            uint4* pad = (uint4*)(sbh + (QBYTES + stg * KVSTG_B + KVTILE_B) / 2
                                      + r * FLD + 64);
            *pad = make_uint4(0x00003C00u, 0u, 0u, 0u);   // {1,0,...} fp16
        }
    }
    __syncthreads();     // Q + pads visible

    uint32_t qf[4][4];
    {
        int rAq = (lane & 7) + ((lane >> 3) & 1) * 8;
        int cAq = ((lane >> 4) & 1) * 8;
#pragma unroll
        for (int ks = 0; ks < 4; ks++) {
            uint32_t off = (uint32_t)((wid * 16 + rAq) * FLD + ks * 16 + cAq) * 2;
            ldsm_x4(qf[ks], aQf + off);
        }
    }

    // loop-invariant ones-column B-fragment (all pad rows identical)
    uint32_t on2[2];
    {
        int rowS = (lane & 15);
        ldsm_x2_t(on2, aQf + QBYTES + KVTILE_B + (uint32_t)(rowS * FLD + 64) * 2);
    }

    float accO[8][4];
    float accS[4] = {0.0f, 0.0f, 0.0f, 0.0f};   // ones-column = row sums
#pragma unroll
    for (int j = 0; j < 8; j++)
#pragma unroll
        for (int q = 0; q < 4; q++) accO[j][q] = 0.0f;
    float m0 = -1e30f, m1 = -1e30f;

    const int rowK = (lane & 7) + ((lane >> 4) & 1) * 8;
    const int colK = ((lane >> 3) & 1) * 8;
    const int rowV = (lane & 15);
    const int colV = (lane >> 4) * 8;

    int stg = 0;
    for (int jt = 0; jt <= jt_end; jt++) {
        if (jt < jt_end) { CP_WAIT1(); }
        else             { CP_WAIT0(); }
        __syncthreads();                          // stage jt ready; jt-1 reads done

        if (jt + 2 <= jt_end) {
            int lstg = stg + 2; if (lstg >= 3) lstg -= 3;
            load_kv(jt + 2, lstg);
        }

        const uint32_t aKf = aQf + QBYTES + (uint32_t)stg * KVSTG_B;
        const uint32_t aVf = aKf + KVTILE_B;

        float s[8][4];
#pragma unroll
        for (int j = 0; j < 8; j++)
#pragma unroll
            for (int q = 0; q < 4; q++) s[j][q] = 0.0f;

        // ---- S = Q @ K^T  (single fp16 product) ----
#pragma unroll
        for (int ks = 0; ks < 4; ks++) {
#pragma unroll
            for (int pr = 0; pr < 4; pr++) {
                uint32_t kf4[4];
                uint32_t off = (uint32_t)((pr * 16 + rowK) * FLD + ks * 16 + colK) * 2;
                ldsm_x4(kf4, aKf + off);
                mma16816h(s[2 * pr],     qf[ks], kf4[0], kf4[1]);
                mma16816h(s[2 * pr + 1], qf[ks], kf4[2], kf4[3]);
            }
        }

        if (jt >= 2 * it) {
            int row0 = it * 128 + wid * 16 + (lane >> 2);
#pragma unroll
            for (int j = 0; j < 8; j++) {
                int col = jt * 64 + j * 8 + (lane & 3) * 2;
                if (col     > row0)     s[j][0] = -1e30f;
                if (col + 1 > row0)     s[j][1] = -1e30f;
                if (col     > row0 + 8) s[j][2] = -1e30f;
                if (col + 1 > row0 + 8) s[j][3] = -1e30f;
            }
        }

        // ---- online softmax (base-2); P -> fp16 ----
        float mx0 = -1e30f, mx1 = -1e30f;
#pragma unroll
        for (int j = 0; j < 8; j++) {
            mx0 = fmaxf(mx0, fmaxf(s[j][0], s[j][1]));
            mx1 = fmaxf(mx1, fmaxf(s[j][2], s[j][3]));
        }
        mx0 = fmaxf(mx0, __shfl_xor_sync(0xffffffffu, mx0, 1));
        mx0 = fmaxf(mx0, __shfl_xor_sync(0xffffffffu, mx0, 2));
        mx1 = fmaxf(mx1, __shfl_xor_sync(0xffffffffu, mx1, 1));
        mx1 = fmaxf(mx1, __shfl_xor_sync(0xffffffffu, mx1, 2));
        float m0n = fmaxf(m0, mx0), m1n = fmaxf(m1, mx1);
        float r0 = exp2f(m0 - m0n);
        float r1 = exp2f(m1 - m1n);
        m0 = m0n; m1 = m1n;

        uint32_t parr[8][2];
#pragma unroll
        for (int j = 0; j < 8; j++) {
            __half2 p01 = __floats2half2_rn(exp2f(s[j][0] - m0n),
                                            exp2f(s[j][1] - m0n));
            __half2 p23 = __floats2half2_rn(exp2f(s[j][2] - m1n),
                                            exp2f(s[j][3] - m1n));
            parr[j][0] = *(uint32_t*)&p01;
            parr[j][1] = *(uint32_t*)&p23;
        }
#pragma unroll
        for (int j = 0; j < 8; j++) {
            accO[j][0] *= r0; accO[j][1] *= r0;
            accO[j][2] *= r1; accO[j][3] *= r1;
        }
        accS[0] *= r0; accS[1] *= r0;
        accS[2] *= r1; accS[3] *= r1;

        // ---- O += P @ V ; accS += P @ ones (invariant fragment) ----
#pragma unroll
        for (int ks = 0; ks < 4; ks++) {
            uint32_t ph[4] = { parr[2 * ks][0], parr[2 * ks][1],
                               parr[2 * ks + 1][0], parr[2 * ks + 1][1] };
#pragma unroll
            for (int dp = 0; dp < 4; dp++) {
                uint32_t vf4[4];
                uint32_t off = (uint32_t)((ks * 16 + rowV) * FLD + dp * 16 + colV) * 2;
                ldsm_x4_t(vf4, aVf + off);
                mma16816h(accO[2 * dp],     ph, vf4[0], vf4[1]);
                mma16816h(accO[2 * dp + 1], ph, vf4[2], vf4[3]);
            }
            mma16816h(accS, ph, on2[0], on2[1]);
        }

        stg++; if (stg >= 3) stg = 0;
    }

    // ---- epilogue: l from accS (ones column, col-0 lanes), O / l ----
    float sum0 = __shfl_sync(0xffffffffu, accS[0], lane & 28);
    float sum1 = __shfl_sync(0xffffffffu, accS[2], lane & 28);
    float i0 = 1.0f / sum0, i1 = 1.0f / sum1;
    const int b = bh >> 4, hh = bh & 15;
    const int t0 = it * 128 + wid * 16 + (lane >> 2);
#pragma unroll
    for (int j = 0; j < 8; j++) {
        int d = hh * 64 + j * 8 + (lane & 3) * 2;
        size_t o0 = (size_t)(b * SEQ + t0) * D_MODEL + d;
        size_t o1 = (size_t)(b * SEQ + t0 + 8) * D_MODEL + d;
        uint32_t hi, lo;
        split2h(accO[j][0] * i0, accO[j][1] * i0, hi, lo);
        *(uint32_t*)(g_Ofh + o0) = hi;
        *(uint32_t*)(g_Ofl + o0) = lo;
        split2h(accO[j][2] * i1, accO[j][3] * i1, hi, lo);
        *(uint32_t*)(g_Ofh + o1) = hi;
        *(uint32_t*)(g_Ofl + o1) = lo;
    }
}

// ---------------- launch ----------------------------------------------------
extern "C" void kernel_launch(void* const* d_in, const int* in_sizes, int n_in,
                              void* d_out, int out_size)
{
    const float* x  = (const float*)d_in[0];
    const float* Wq = (const float*)d_in[1];
    const float* Wk = (const float*)d_in[2];
    const float* Wv = (const float*)d_in[3];
    const float* Wo = (const float*)d_in[4];
    float* out = (float*)d_out;

    cudaFuncSetAttribute(gemm_fp16_kernel,
                         cudaFuncAttributeMaxDynamicSharedMemorySize, GEMM_SMEM);
    cudaFuncSetAttribute(flash_mma_kernel,
                         cudaFuncAttributeMaxDynamicSharedMemorySize, FA_SMEM);

    // 0) pre-split inputs to fp16 (single merged kernel)
    split_all_kernel<<<12288, 256>>>(x, Wq, Wk, Wv, Wo);

    // 1) fused QKV projections (grid.z selects weight slot)
    dim3 gq(D_MODEL / 128, M_ROWS / 128, 3);
    gemm_fp16_kernel<<<gq, 256, GEMM_SMEM>>>(0, nullptr);

    // 2) RoPE: Q -> fp16 (x 0.125*log2e), K -> fp16
    rope_split_kernel<<<(BATCH * N_HEADS * SEQ * 32) / 256, 256>>>();

    // 3) causal flash attention (fp16 HMMA, 3-stage pipeline)
    flash_mma_kernel<<<dim3(SEQ / 128, BATCH * N_HEADS), 256, FA_SMEM>>>();

    // 4) output projection: out = O @ Wo^T
    dim3 go(D_MODEL / 128, M_ROWS / 128, 1);
    gemm_fp16_kernel<<<go, 256, GEMM_SMEM>>>(1, out);
}